// round 11
// baseline (speedup 1.0000x reference)
#include <cuda_runtime.h>
#include <cuda_bf16.h>
#include <cuda_fp16.h>
#include <math.h>
#include <stdint.h>

// ---------------- problem constants ----------------
#define NH    768            // H
#define HEADS 8
#define HO    6144           // HEADS*H
#define TSTEP 3
#define BB    128            // molecules
#define NATOM 48
#define NPG   49             // nodes per graph
#define EPG   144            // edges per graph
#define NN    6272           // B*NPG nodes
#define EE    18432          // B*EPG edges
#define H3    2304           // 3*H

// ---------------- device scratch (no allocation allowed) ----------------
__device__ float  g_h   [(size_t)NN * NH];    // current node features (fp32)
__device__ __half g_fsh [(size_t)NN * HO];    // feat_src  [N, heads*H] fp16
__device__ __half g_fdh [(size_t)NN * HO];    // feat_dst  [N, heads*H] fp16
__device__ float  g_logit[(size_t)EE * HEADS];
__device__ float  g_amean[(size_t)EE];
__device__ float  g_mol [(size_t)BB * NH];
__device__ float  g_gi  [(size_t)BB * H3];
__device__ float  g_gh  [(size_t)BB * H3];

// fp16 operands for tensor-core GEMM
__device__ __half g_Af [(size_t)NN * NH];     // A in fp16
__device__ __half g_Bf [(size_t)6 * HO * NH]; // 6 weight mats, [N=6144,K=768] fp16
__device__ __half g_ah [(size_t)TSTEP * HEADS * NH];   // attn_a in fp16

// ---------------- init ----------------
__global__ void init_k(const float* __restrict__ h_nodes, const float* __restrict__ mol)
{
    long i = (long)blockIdx.x * 256 + threadIdx.x;
    const long tot = (long)NN * NH;
    if (i < tot) {
        float v = h_nodes[i];
        g_h[i] = v;
        g_Af[i] = __float2half_rn(v);
    } else if (i < tot + (long)BB * NH) {
        g_mol[i - tot] = mol[i - tot];
    }
}

// ---------------- attn_a -> fp16 ----------------
__global__ void conv_attn_k(const float* __restrict__ attn_a)
{
    int i = blockIdx.x * 256 + threadIdx.x;
    if (i < TSTEP * HEADS * NH) g_ah[i] = __float2half_rn(attn_a[i]);
}

// ---------------- transpose + fp16-convert weight matrices ----------------
__global__ void transpose_conv_k(const float* __restrict__ Wsrc, const float* __restrict__ Wdst)
{
    const int mat = blockIdx.z;                    // t*2 + sel
    const float* W = ((mat & 1) ? Wdst : Wsrc) + (size_t)(mat >> 1) * NH * HO;
    __shared__ float tile[32][33];
    const int n0 = blockIdx.x * 32, k0 = blockIdx.y * 32;
    const int tx = threadIdx.x, ty = threadIdx.y;  // 32 x 8
    #pragma unroll
    for (int i = ty; i < 32; i += 8)
        tile[i][tx] = W[(size_t)(k0 + i) * HO + n0 + tx];
    __syncthreads();
    const size_t base = (size_t)mat * HO * NH;
    #pragma unroll
    for (int i = ty; i < 32; i += 8)
        g_Bf[base + (size_t)(n0 + i) * NH + k0 + tx] = __float2half_rn(tile[tx][i]);
}

// ================= mma.sync fp16 GEMM: block 128x256, warp 64x64 ==========
// C = A * B^T, fp16 in / fp32 accum. K-chunk 32, 6-stage cp.async pipeline,
// 8 warps (2m x 4n). gridDim.z selects fs/fd. 1 CTA/SM, 144 KB smem.

#define KC      32
#define ST_AF   0
#define ST_BF   8192                       // A tile = 128 rows x 64B = 8 KB
#define ST_SZ   24576                      // + B tile 256 rows x 64B = 16 KB
#define NSTAGE  6
#define GEMM_SMEM (NSTAGE * ST_SZ)         // 144 KB

__device__ __forceinline__ void cp16(uint32_t saddr, const void* gaddr) {
    asm volatile("cp.async.cg.shared.global [%0], [%1], 16;" :: "r"(saddr), "l"(gaddr) : "memory");
}
__device__ __forceinline__ void cp_commit() { asm volatile("cp.async.commit_group;" ::: "memory"); }
template <int N> __device__ __forceinline__ void cp_wait() {
    asm volatile("cp.async.wait_group %0;" :: "n"(N) : "memory");
}
__device__ __forceinline__ void ldsm4(uint32_t r[4], uint32_t addr) {
    asm volatile("ldmatrix.sync.aligned.m8n8.x4.shared.b16 {%0,%1,%2,%3}, [%4];"
        : "=r"(r[0]), "=r"(r[1]), "=r"(r[2]), "=r"(r[3]) : "r"(addr));
}
__device__ __forceinline__ void mma_f16(float c[4], const uint32_t a[4], const uint32_t b[2]) {
    asm volatile("mma.sync.aligned.m16n8k16.row.col.f32.f16.f16.f32 "
        "{%0,%1,%2,%3}, {%4,%5,%6,%7}, {%8,%9}, {%0,%1,%2,%3};"
        : "+f"(c[0]), "+f"(c[1]), "+f"(c[2]), "+f"(c[3])
        : "r"(a[0]), "r"(a[1]), "r"(a[2]), "r"(a[3]), "r"(b[0]), "r"(b[1]));
}
__device__ __forceinline__ uint32_t smem_u32(const void* p) {
    uint32_t a;
    asm("{ .reg .u64 t; cvta.to.shared.u64 t, %1; cvt.u32.u64 %0, t; }" : "=r"(a) : "l"(p));
    return a;
}

__global__ __launch_bounds__(256, 1) void gemm_mma(
    const __half* __restrict__ Bf_base,
    const float* __restrict__ bias_src, const float* __restrict__ bias_dst)
{
    extern __shared__ char sm[];
    const uint32_t sb = smem_u32(sm);
    const int tid  = threadIdx.x;
    const int wid  = tid >> 5, lane = tid & 31;
    const int m0   = blockIdx.y * 128, n0 = blockIdx.x * 256;
    const int sel  = blockIdx.z;
    const size_t msz = (size_t)HO * NH;
    const __half* __restrict__ Bf = Bf_base + (size_t)sel * msz;
    const float* __restrict__ bias = sel ? bias_dst : bias_src;
    __half* __restrict__ C = sel ? g_fdh : g_fsh;
    const int wm   = wid & 1;           // 0..1 -> 64-row slice
    const int wn   = wid >> 1;          // 0..3 -> 64-col slice

    // cp.async loader (KC=32 -> 4 segs of 16B per row; swizzle seg ^= row&3)
    // A: 512 segs -> 2 per thread; B: 1024 segs -> 4 per thread
    #define LOAD_STAGE(stg, k0) do {                                              \
        uint32_t _b = sb + (stg) * ST_SZ;                                         \
        _Pragma("unroll")                                                         \
        for (int l = 0; l < 2; l++) {                                             \
            int f = tid * 2 + l;                                                  \
            int r = f >> 2, sg = f & 3;                                           \
            uint32_t sw = (uint32_t)(r * 64 + ((sg ^ (r & 3)) << 4));             \
            cp16(_b + ST_AF + sw, g_Af + (size_t)(m0 + r) * NH + (k0) + sg * 8);  \
        }                                                                         \
        _Pragma("unroll")                                                         \
        for (int l = 0; l < 4; l++) {                                             \
            int f = tid * 4 + l;                                                  \
            int r = f >> 2, sg = f & 3;                                           \
            uint32_t sw = (uint32_t)(r * 64 + ((sg ^ (r & 3)) << 4));             \
            cp16(_b + ST_BF + sw, Bf + (size_t)(n0 + r) * NH + (k0) + sg * 8);    \
        }                                                                         \
    } while (0)

    // per-lane ldmatrix addressing
    const int sub = lane >> 3, rin = lane & 7;
    const int aRow0 = wm * 64 + (sub & 1) * 8 + rin;   // + mf*16 (mf 0..3)
    const int aSegB = sub >> 1;
    const int bRow0 = wn * 64 + (sub >> 1) * 8 + rin;  // + pp*16 (pp 0..3)
    const int bSegB = sub & 1;

    float acc[32][4];                                  // [mf*8 + p][4]
    #pragma unroll
    for (int i = 0; i < 32; i++)
        #pragma unroll
        for (int j = 0; j < 4; j++) acc[i][j] = 0.f;

    #pragma unroll
    for (int s = 0; s < NSTAGE - 1; s++) {
        LOAD_STAGE(s, s * KC);
        cp_commit();
    }

    const int NCH = NH / KC;   // 24
    int stg = 0;
    for (int kc = 0; kc < NCH; kc++) {
        cp_wait<NSTAGE - 2>();
        __syncthreads();
        if (kc + NSTAGE - 1 < NCH) {
            LOAD_STAGE((kc + NSTAGE - 1) % NSTAGE, (kc + NSTAGE - 1) * KC);
        }
        cp_commit();   // uniform group counting

        const uint32_t stb = sb + stg * ST_SZ;
        #pragma unroll
        for (int k16 = 0; k16 < 2; k16++) {
            const int ks = k16 * 2;
            uint32_t aF[4][4], bb[8][2];
            #pragma unroll
            for (int mf = 0; mf < 4; mf++) {
                int row = aRow0 + mf * 16;
                uint32_t off = row * 64 + (((ks + aSegB) ^ (row & 3)) << 4);
                ldsm4(aF[mf], stb + ST_AF + off);
            }
            #pragma unroll
            for (int pp = 0; pp < 4; pp++) {
                int row = bRow0 + pp * 16;
                uint32_t off = row * 64 + (((ks + bSegB) ^ (row & 3)) << 4);
                uint32_t t[4];
                ldsm4(t, stb + ST_BF + off);
                bb[pp * 2][0] = t[0]; bb[pp * 2][1] = t[1];
                bb[pp * 2 + 1][0] = t[2]; bb[pp * 2 + 1][1] = t[3];
            }
            #pragma unroll
            for (int mf = 0; mf < 4; mf++)
                #pragma unroll
                for (int p = 0; p < 8; p++) mma_f16(acc[mf * 8 + p], aF[mf], bb[p]);
        }
        stg = (stg + 1 == NSTAGE) ? 0 : stg + 1;
    }

    // epilogue: C = fp16(acc + bias)
    const int qrow = lane >> 2, qcol = (lane & 3) * 2;
    const int gmb = m0 + wm * 64;
    const int gnb = n0 + wn * 64;
    #pragma unroll
    for (int mf = 0; mf < 4; mf++) {
        int r0 = gmb + mf * 16 + qrow;
        #pragma unroll
        for (int p = 0; p < 8; p++) {
            int cn = gnb + p * 8 + qcol;
            float bx = bias[cn], by = bias[cn + 1];
            __half2 v0 = __floats2half2_rn(acc[mf * 8 + p][0] + bx, acc[mf * 8 + p][1] + by);
            __half2 v1 = __floats2half2_rn(acc[mf * 8 + p][2] + bx, acc[mf * 8 + p][3] + by);
            *(__half2*)&C[(size_t)r0 * HO + cn] = v0;
            *(__half2*)&C[(size_t)(r0 + 8) * HO + cn] = v1;
        }
    }
    #undef LOAD_STAGE
}

// ---------------- edge logits: per (edge, head) warp, uint4 + half2 math ----------------
__global__ void edge_logits_k(const int* __restrict__ src, const int* __restrict__ dst,
                              const __half* __restrict__ aa_t)
{
    const int e = blockIdx.x;
    const int w = threadIdx.x >> 5, lane = threadIdx.x & 31;
    const int s = src[e], d = dst[e];
    const uint4* fsr = (const uint4*)(g_fsh + (size_t)s * HO + w * NH);
    const uint4* fdr = (const uint4*)(g_fdh + (size_t)d * HO + w * NH);
    const uint4* aar = (const uint4*)(aa_t + (size_t)w * NH);
    const __half2 hz  = __float2half2_rn(0.f);
    const __half2 hsl = __float2half2_rn(0.2f);
    float acc = 0.f;
    #pragma unroll
    for (int it = 0; it < 3; it++) {
        int idx = it * 32 + lane;        // 0..95 (96 uint4 = 768 halves)
        uint4 A = fsr[idx], D = fdr[idx], V = aar[idx];
        const __half2* hA = (const __half2*)&A;
        const __half2* hD = (const __half2*)&D;
        const __half2* hV = (const __half2*)&V;
        #pragma unroll
        for (int j = 0; j < 4; j++) {
            __half2 x  = __hadd2(hA[j], hD[j]);
            __half2 lk = __hfma2(__hmin2(x, hz), hsl, __hmax2(x, hz));
            float2 f = __half22float2(__hmul2(lk, hV[j]));
            acc += f.x + f.y;
        }
    }
    #pragma unroll
    for (int o = 16; o > 0; o >>= 1) acc += __shfl_xor_sync(0xFFFFFFFFu, acc, o);
    if (lane == 0) g_logit[(size_t)e * HEADS + w] = acc;
}

// ---------------- per-node softmax + aggregation (no atomics) ----------------
__global__ __launch_bounds__(256) void node_aggregate_k(
    const int* __restrict__ src, const int* __restrict__ dst)
{
    const int n = blockIdx.x;
    const int tid = threadIdx.x;
    __shared__ int   cnt;
    __shared__ int   eidx[EPG];
    __shared__ int   esrc[EPG];
    __shared__ float w[EPG];
    __shared__ float am[EPG];
    __shared__ float red[256];

    const int g = n / NPG;
    if (tid == 0) cnt = 0;
    __syncthreads();
    if (tid < EPG) {
        int e = g * EPG + tid;
        if (dst[e] == n) {
            int p = atomicAdd(&cnt, 1);
            eidx[p] = e;
            esrc[p] = src[e];
        }
    }
    __syncthreads();
    const int deg = cnt;

    float h0 = 0.f, h1 = 0.f, h2 = 0.f;

    if (deg > 0) {
        for (int hh = 0; hh < HEADS; hh++) {
            float lm = -1e30f;
            for (int i = tid; i < deg; i += 256)
                lm = fmaxf(lm, g_logit[(size_t)eidx[i] * HEADS + hh]);
            red[tid] = lm; __syncthreads();
            for (int s2 = 128; s2 > 0; s2 >>= 1) {
                if (tid < s2) red[tid] = fmaxf(red[tid], red[tid + s2]);
                __syncthreads();
            }
            float m = red[0]; __syncthreads();
            float ls = 0.f;
            for (int i = tid; i < deg; i += 256) {
                float ex = expf(g_logit[(size_t)eidx[i] * HEADS + hh] - m);
                w[i] = ex; ls += ex;
            }
            red[tid] = ls; __syncthreads();
            for (int s2 = 128; s2 > 0; s2 >>= 1) {
                if (tid < s2) red[tid] += red[tid + s2];
                __syncthreads();
            }
            float inv = 1.f / red[0]; __syncthreads();
            for (int i = tid; i < deg; i += 256) {
                float wi = w[i] * inv;
                w[i] = wi;
                float prev = (hh == 0) ? 0.f : am[i];
                am[i] = prev + wi * 0.125f;
            }
            __syncthreads();
            const int bh = hh * NH;
            for (int e = 0; e < deg; e++) {
                float we = w[e];
                const __half* fr = &g_fsh[(size_t)esrc[e] * HO + bh];
                h0 = fmaf(we, __half2float(fr[tid      ]), h0);
                h1 = fmaf(we, __half2float(fr[tid + 256]), h1);
                h2 = fmaf(we, __half2float(fr[tid + 512]), h2);
            }
            __syncthreads();
        }
    }
    {
        size_t base = (size_t)n * NH;
        float v;
        v = h0 * 0.125f; g_h[base + tid]       = v; g_Af[base + tid]       = __float2half_rn(v);
        v = h1 * 0.125f; g_h[base + tid + 256] = v; g_Af[base + tid + 256] = __float2half_rn(v);
        v = h2 * 0.125f; g_h[base + tid + 512] = v; g_Af[base + tid + 512] = __float2half_rn(v);
    }
    for (int i = tid; i < deg; i += 256) g_amean[eidx[i]] = am[i];
}

// ---------------- attention gather to output ----------------
__global__ void attn_gather_k(const int* __restrict__ eids, float* __restrict__ out, int t)
{
    int i = blockIdx.x * 256 + threadIdx.x;
    if (i < BB * NATOM)
        out[(size_t)BB * NH + (size_t)t * BB * NATOM + i] = g_amean[eids[i]];
}

// ---------------- GRU projections: tiled fp32 GEMM ----------------
__global__ __launch_bounds__(256) void gru_gemm_k(
    const float* __restrict__ W_ih, const float* __restrict__ W_hh,
    const float* __restrict__ b_ih, const float* __restrict__ b_hh,
    const int* __restrict__ vnid)
{
    __shared__ float As[32][132];
    __shared__ float Bs[32][68];
    const int jb  = blockIdx.x * 64;        // 72 blocks
    const int sel = (jb >= H3) ? 1 : 0;
    const int j0  = sel ? jb - H3 : jb;
    const float* __restrict__ W    = sel ? W_hh : W_ih;
    const float* __restrict__ bias = sel ? b_hh : b_ih;
    float* __restrict__ Cout       = sel ? g_gh : g_gi;

    const int tid = threadIdx.x;
    const int ty = tid >> 4, tx = tid & 15;
    float acc[8][4];
    #pragma unroll
    for (int i = 0; i < 8; i++)
        #pragma unroll
        for (int j = 0; j < 4; j++) acc[i][j] = 0.f;

    for (int k0 = 0; k0 < NH; k0 += 32) {
        #pragma unroll
        for (int l = 0; l < 4; l++) {
            int f = tid * 4 + l;
            int r = f >> 3;
            int kv = (f & 7) * 4;
            const float* arow = sel ? (g_mol + (size_t)r * NH)
                                    : (g_h + (size_t)vnid[r] * NH);
            float4 v = *(const float4*)(arow + k0 + kv);
            As[kv + 0][r] = v.x; As[kv + 1][r] = v.y;
            As[kv + 2][r] = v.z; As[kv + 3][r] = v.w;
        }
        #pragma unroll
        for (int l = 0; l < 2; l++) {
            int f = tid * 2 + l;
            int c = f >> 3;
            int kv = (f & 7) * 4;
            float4 v = *(const float4*)(W + (size_t)(j0 + c) * NH + k0 + kv);
            Bs[kv + 0][c] = v.x; Bs[kv + 1][c] = v.y;
            Bs[kv + 2][c] = v.z; Bs[kv + 3][c] = v.w;
        }
        __syncthreads();
        #pragma unroll
        for (int k = 0; k < 32; k++) {
            float a[8], b[4];
            *(float4*)&a[0] = *(float4*)&As[k][ty * 8];
            *(float4*)&a[4] = *(float4*)&As[k][ty * 8 + 4];
            *(float4*)&b[0] = *(float4*)&Bs[k][tx * 4];
            #pragma unroll
            for (int i = 0; i < 8; i++)
                #pragma unroll
                for (int j = 0; j < 4; j++)
                    acc[i][j] = fmaf(a[i], b[j], acc[i][j]);
        }
        __syncthreads();
    }
    #pragma unroll
    for (int i = 0; i < 8; i++) {
        int b = ty * 8 + i;
        #pragma unroll
        for (int j = 0; j < 4; j++) {
            int jj = j0 + tx * 4 + j;
            Cout[(size_t)b * H3 + jj] = acc[i][j] + bias[jj];
        }
    }
}

// ---------------- GRU combine + relu ----------------
__global__ void gru_combine_k(float* __restrict__ out_mol, int write_out)
{
    int i = blockIdx.x * 256 + threadIdx.x;
    int b = i / NH, k = i % NH;
    size_t base = (size_t)b * H3;
    float ir = g_gi[base + k], iz = g_gi[base + NH + k], in_ = g_gi[base + 2 * NH + k];
    float hr = g_gh[base + k], hz = g_gh[base + NH + k], hn  = g_gh[base + 2 * NH + k];
    float r  = 1.f / (1.f + expf(-(ir + hr)));
    float z  = 1.f / (1.f + expf(-(iz + hz)));
    float nn = tanhf(in_ + r * hn);
    float hprev = g_mol[i];
    float hnew  = (1.f - z) * nn + z * hprev;
    hnew = fmaxf(hnew, 0.f);
    g_mol[i] = hnew;
    if (write_out) out_mol[i] = hnew;
}

// ---------------- launch ----------------
extern "C" void kernel_launch(void* const* d_in, const int* in_sizes, int n_in,
                              void* d_out, int out_size)
{
    const float* h_nodes  = (const float*)d_in[0];
    const float* mol_feat = (const float*)d_in[1];
    const float* W_src    = (const float*)d_in[2];
    const float* b_src    = (const float*)d_in[3];
    const float* W_dst    = (const float*)d_in[4];
    const float* b_dst    = (const float*)d_in[5];
    const float* attn_a   = (const float*)d_in[6];
    const float* W_ih     = (const float*)d_in[7];
    const float* W_hh     = (const float*)d_in[8];
    const float* b_ih     = (const float*)d_in[9];
    const float* b_hh     = (const float*)d_in[10];
    const int*   src      = (const int*)d_in[11];
    const int*   dst      = (const int*)d_in[12];
    const int*   vnid     = (const int*)d_in[13];
    const int*   eids     = (const int*)d_in[14];
    float* out = (float*)d_out;

    cudaFuncSetAttribute(gemm_mma, cudaFuncAttributeMaxDynamicSharedMemorySize, GEMM_SMEM);

    {
        long tot = (long)NN * NH + (long)BB * NH;
        init_k<<<(int)((tot + 255) / 256), 256>>>(h_nodes, mol_feat);
    }
    {
        dim3 gr(HO / 32, NH / 32, 6);
        transpose_conv_k<<<gr, dim3(32, 8)>>>(W_src, W_dst);
    }
    conv_attn_k<<<(TSTEP * HEADS * NH + 255) / 256, 256>>>(attn_a);

    __half* pBf = nullptr;
    cudaGetSymbolAddress((void**)&pBf, g_Bf);
    __half* pAh = nullptr;
    cudaGetSymbolAddress((void**)&pAh, g_ah);

    for (int t = 0; t < TSTEP; t++) {
        dim3 gg(HO / 256, NN / 128, 2);   // (24, 49, 2)
        size_t msz = (size_t)HO * NH;
        gemm_mma<<<gg, 256, GEMM_SMEM>>>(pBf + (size_t)(t * 2) * msz,
                                         b_src + (size_t)t * HO,
                                         b_dst + (size_t)t * HO);
        edge_logits_k<<<EE, 256>>>(src, dst, pAh + (size_t)t * HEADS * NH);
        node_aggregate_k<<<NN, 256>>>(src, dst);
        attn_gather_k<<<(BB * NATOM + 255) / 256, 256>>>(eids, out, t);
        gru_gemm_k<<<(H3 * 2) / 64, 256>>>(W_ih + (size_t)t * H3 * NH,
                                           W_hh + (size_t)t * H3 * NH,
                                           b_ih + (size_t)t * H3,
                                           b_hh + (size_t)t * H3, vnid);
        gru_combine_k<<<BB * NH / 256, 256>>>(out, t == TSTEP - 1);
    }
}

// round 12
// speedup vs baseline: 1.2794x; 1.2794x over previous
#include <cuda_runtime.h>
#include <cuda_bf16.h>
#include <cuda_fp16.h>
#include <math.h>
#include <stdint.h>

// ---------------- problem constants ----------------
#define NH    768            // H
#define HEADS 8
#define HO    6144           // HEADS*H
#define TSTEP 3
#define BB    128            // molecules
#define NATOM 48
#define NPG   49             // nodes per graph
#define EPG   144            // edges per graph
#define NN    6272           // B*NPG nodes
#define EE    18432          // B*EPG edges
#define H3    2304           // 3*H

// ---------------- device scratch (no allocation allowed) ----------------
__device__ float  g_h   [(size_t)NN * NH];    // current node features (fp32)
__device__ __half g_fsh [(size_t)NN * HO];    // feat_src  [N, heads*H] fp16
__device__ __half g_fdh [(size_t)NN * HO];    // feat_dst  [N, heads*H] fp16
__device__ float  g_logit[(size_t)EE * HEADS];
__device__ float  g_amean[(size_t)EE];
__device__ float  g_mol [(size_t)BB * NH];
__device__ float  g_gi  [(size_t)BB * H3];
__device__ float  g_gh  [(size_t)BB * H3];

// fp16 operands for tensor-core GEMM
__device__ __half g_Af [(size_t)NN * NH];     // A in fp16
__device__ __half g_Bf [(size_t)6 * HO * NH]; // 6 weight mats, [N=6144,K=768] fp16
__device__ __half g_ah [(size_t)TSTEP * HEADS * NH];   // attn_a in fp16

// ---------------- init ----------------
__global__ void init_k(const float* __restrict__ h_nodes, const float* __restrict__ mol)
{
    long i = (long)blockIdx.x * 256 + threadIdx.x;
    const long tot = (long)NN * NH;
    if (i < tot) {
        float v = h_nodes[i];
        g_h[i] = v;
        g_Af[i] = __float2half_rn(v);
    } else if (i < tot + (long)BB * NH) {
        g_mol[i - tot] = mol[i - tot];
    }
}

// ---------------- attn_a -> fp16 ----------------
__global__ void conv_attn_k(const float* __restrict__ attn_a)
{
    int i = blockIdx.x * 256 + threadIdx.x;
    if (i < TSTEP * HEADS * NH) g_ah[i] = __float2half_rn(attn_a[i]);
}

// ---------------- transpose + fp16-convert weight matrices ----------------
__global__ void transpose_conv_k(const float* __restrict__ Wsrc, const float* __restrict__ Wdst)
{
    const int mat = blockIdx.z;                    // t*2 + sel
    const float* W = ((mat & 1) ? Wdst : Wsrc) + (size_t)(mat >> 1) * NH * HO;
    __shared__ float tile[32][33];
    const int n0 = blockIdx.x * 32, k0 = blockIdx.y * 32;
    const int tx = threadIdx.x, ty = threadIdx.y;  // 32 x 8
    #pragma unroll
    for (int i = ty; i < 32; i += 8)
        tile[i][tx] = W[(size_t)(k0 + i) * HO + n0 + tx];
    __syncthreads();
    const size_t base = (size_t)mat * HO * NH;
    #pragma unroll
    for (int i = ty; i < 32; i += 8)
        g_Bf[base + (size_t)(n0 + i) * NH + k0 + tx] = __float2half_rn(tile[tx][i]);
}

// ================= mma.sync fp16 GEMM (R10 proven config) ==========
// C = A * B^T, single-pass fp16, fp32 accum. Block tile 128x128, K-chunk 32,
// 6-stage cp.async pipeline, 8 warps (4m x 2n). gridDim.z selects fs/fd.

#define KC      32
#define ST_AF   0
#define ST_BF   8192
#define ST_SZ   16384                      // per stage (2 tiles x 8KB)
#define NSTAGE  6
#define GEMM_SMEM (NSTAGE * ST_SZ)         // 96 KB

__device__ __forceinline__ void cp16(uint32_t saddr, const void* gaddr) {
    asm volatile("cp.async.cg.shared.global [%0], [%1], 16;" :: "r"(saddr), "l"(gaddr) : "memory");
}
__device__ __forceinline__ void cp_commit() { asm volatile("cp.async.commit_group;" ::: "memory"); }
template <int N> __device__ __forceinline__ void cp_wait() {
    asm volatile("cp.async.wait_group %0;" :: "n"(N) : "memory");
}
__device__ __forceinline__ void ldsm4(uint32_t r[4], uint32_t addr) {
    asm volatile("ldmatrix.sync.aligned.m8n8.x4.shared.b16 {%0,%1,%2,%3}, [%4];"
        : "=r"(r[0]), "=r"(r[1]), "=r"(r[2]), "=r"(r[3]) : "r"(addr));
}
__device__ __forceinline__ void mma_f16(float c[4], const uint32_t a[4], const uint32_t b[2]) {
    asm volatile("mma.sync.aligned.m16n8k16.row.col.f32.f16.f16.f32 "
        "{%0,%1,%2,%3}, {%4,%5,%6,%7}, {%8,%9}, {%0,%1,%2,%3};"
        : "+f"(c[0]), "+f"(c[1]), "+f"(c[2]), "+f"(c[3])
        : "r"(a[0]), "r"(a[1]), "r"(a[2]), "r"(a[3]), "r"(b[0]), "r"(b[1]));
}
__device__ __forceinline__ uint32_t smem_u32(const void* p) {
    uint32_t a;
    asm("{ .reg .u64 t; cvta.to.shared.u64 t, %1; cvt.u32.u64 %0, t; }" : "=r"(a) : "l"(p));
    return a;
}

__global__ __launch_bounds__(256, 2) void gemm_mma(
    const __half* __restrict__ Bf_base,
    const float* __restrict__ bias_src, const float* __restrict__ bias_dst)
{
    extern __shared__ char sm[];
    const uint32_t sb = smem_u32(sm);
    const int tid  = threadIdx.x;
    const int wid  = tid >> 5, lane = tid & 31;
    const int m0   = blockIdx.y * 128, n0 = blockIdx.x * 128;
    const int sel  = blockIdx.z;
    const size_t msz = (size_t)HO * NH;
    const __half* __restrict__ Bf = Bf_base + (size_t)sel * msz;
    const float* __restrict__ bias = sel ? bias_dst : bias_src;
    __half* __restrict__ C = sel ? g_fdh : g_fsh;
    const int wm   = wid & 3;           // 0..3 -> 32-row slice
    const int wn   = wid >> 2;          // 0..1 -> 64-col slice

    // cp.async loader: thread -> 2 (row,seg) pairs, 2 tiles each
    const int seg0 = tid * 2;
    const int r0l  = seg0 >> 2,  c0l = seg0 & 3;
    const int r1l  = (seg0 + 1) >> 2, c1l = (seg0 + 1) & 3;
    const uint32_t so0 = r0l * 64 + ((c0l ^ (r0l & 3)) << 4);
    const uint32_t so1 = r1l * 64 + ((c1l ^ (r1l & 3)) << 4);

    #define LOAD_STAGE(stg, k0) do {                                              \
        uint32_t _b = sb + (stg) * ST_SZ;                                         \
        size_t ga0 = (size_t)(m0 + r0l) * NH + (k0) + c0l * 8;                    \
        size_t ga1 = (size_t)(m0 + r1l) * NH + (k0) + c1l * 8;                    \
        size_t gb0 = (size_t)(n0 + r0l) * NH + (k0) + c0l * 8;                    \
        size_t gb1 = (size_t)(n0 + r1l) * NH + (k0) + c1l * 8;                    \
        cp16(_b + ST_AF + so0, g_Af + ga0);                                       \
        cp16(_b + ST_AF + so1, g_Af + ga1);                                       \
        cp16(_b + ST_BF + so0, Bf + gb0);                                         \
        cp16(_b + ST_BF + so1, Bf + gb1);                                         \
    } while (0)

    // per-lane ldmatrix addressing
    const int sub = lane >> 3, rin = lane & 7;
    const int aRow0 = wm * 32 + (sub & 1) * 8 + rin;   // + mf*16
    const int aSegB = sub >> 1;
    const int bRow0 = wn * 64 + (sub >> 1) * 8 + rin;  // + p*16
    const int bSegB = sub & 1;

    float acc[16][4];
    #pragma unroll
    for (int i = 0; i < 16; i++)
        #pragma unroll
        for (int j = 0; j < 4; j++) acc[i][j] = 0.f;

    #pragma unroll
    for (int s = 0; s < NSTAGE - 1; s++) {
        LOAD_STAGE(s, s * KC);
        cp_commit();
    }

    const int NCH = NH / KC;   // 24
    int stg = 0;
    for (int kc = 0; kc < NCH; kc++) {
        cp_wait<NSTAGE - 2>();
        __syncthreads();
        if (kc + NSTAGE - 1 < NCH) {
            LOAD_STAGE((kc + NSTAGE - 1) % NSTAGE, (kc + NSTAGE - 1) * KC);
        }
        cp_commit();   // uniform group counting

        const uint32_t stb = sb + stg * ST_SZ;
        #pragma unroll
        for (int k16 = 0; k16 < 2; k16++) {
            const int ks = k16 * 2;
            uint32_t aF[2][4], bb[8][2];
            #pragma unroll
            for (int mf = 0; mf < 2; mf++) {
                int row = aRow0 + mf * 16;
                uint32_t off = row * 64 + (((ks + aSegB) ^ (row & 3)) << 4);
                ldsm4(aF[mf], stb + ST_AF + off);
            }
            #pragma unroll
            for (int pp = 0; pp < 4; pp++) {
                int row = bRow0 + pp * 16;
                uint32_t off = row * 64 + (((ks + bSegB) ^ (row & 3)) << 4);
                uint32_t t[4];
                ldsm4(t, stb + ST_BF + off);
                bb[pp * 2][0] = t[0]; bb[pp * 2][1] = t[1];
                bb[pp * 2 + 1][0] = t[2]; bb[pp * 2 + 1][1] = t[3];
            }
            #pragma unroll
            for (int mf = 0; mf < 2; mf++)
                #pragma unroll
                for (int p = 0; p < 8; p++) mma_f16(acc[mf * 8 + p], aF[mf], bb[p]);
        }
        stg = (stg + 1 == NSTAGE) ? 0 : stg + 1;
    }

    // epilogue: C = fp16(acc + bias)
    const int qrow = lane >> 2, qcol = (lane & 3) * 2;
    const int gmb = m0 + wm * 32;
    const int gnb = n0 + wn * 64;
    #pragma unroll
    for (int mf = 0; mf < 2; mf++) {
        int r0 = gmb + mf * 16 + qrow;
        #pragma unroll
        for (int p = 0; p < 8; p++) {
            int cn = gnb + p * 8 + qcol;
            float bx = bias[cn], by = bias[cn + 1];
            __half2 v0 = __floats2half2_rn(acc[mf * 8 + p][0] + bx, acc[mf * 8 + p][1] + by);
            __half2 v1 = __floats2half2_rn(acc[mf * 8 + p][2] + bx, acc[mf * 8 + p][3] + by);
            *(__half2*)&C[(size_t)r0 * HO + cn] = v0;
            *(__half2*)&C[(size_t)(r0 + 8) * HO + cn] = v1;
        }
    }
    #undef LOAD_STAGE
}

// ---------------- edge logits: per (edge, head) warp, uint4 + half2 math ----------------
__global__ void edge_logits_k(const int* __restrict__ src, const int* __restrict__ dst,
                              const __half* __restrict__ aa_t)
{
    const int e = blockIdx.x;
    const int w = threadIdx.x >> 5, lane = threadIdx.x & 31;
    const int s = src[e], d = dst[e];
    const uint4* fsr = (const uint4*)(g_fsh + (size_t)s * HO + w * NH);
    const uint4* fdr = (const uint4*)(g_fdh + (size_t)d * HO + w * NH);
    const uint4* aar = (const uint4*)(aa_t + (size_t)w * NH);
    const __half2 hz  = __float2half2_rn(0.f);
    const __half2 hsl = __float2half2_rn(0.2f);
    float acc = 0.f;
    #pragma unroll
    for (int it = 0; it < 3; it++) {
        int idx = it * 32 + lane;        // 96 uint4 = 768 halves
        uint4 A = fsr[idx], D = fdr[idx], V = aar[idx];
        const __half2* hA = (const __half2*)&A;
        const __half2* hD = (const __half2*)&D;
        const __half2* hV = (const __half2*)&V;
        #pragma unroll
        for (int j = 0; j < 4; j++) {
            __half2 x  = __hadd2(hA[j], hD[j]);
            __half2 lk = __hfma2(__hmin2(x, hz), hsl, __hmax2(x, hz));
            float2 f = __half22float2(__hmul2(lk, hV[j]));
            acc += f.x + f.y;
        }
    }
    #pragma unroll
    for (int o = 16; o > 0; o >>= 1) acc += __shfl_xor_sync(0xFFFFFFFFu, acc, o);
    if (lane == 0) g_logit[(size_t)e * HEADS + w] = acc;
}

// ---------------- per-node softmax + aggregation ----------------
// Phase 1: warp w = head w, warp-local softmax (no block barriers).
// Phase 2: single fused pass over (edges x heads) with half2 loads.
__global__ __launch_bounds__(256) void node_aggregate_k(
    const int* __restrict__ src, const int* __restrict__ dst)
{
    const int n = blockIdx.x;
    const int tid = threadIdx.x;
    const int wid = tid >> 5, lane = tid & 31;
    __shared__ int   cnt;
    __shared__ int   eidx[EPG];
    __shared__ int   esrc[EPG];
    __shared__ float wsm[HEADS][EPG];

    const int g = n / NPG;
    if (tid == 0) cnt = 0;
    __syncthreads();
    if (tid < EPG) {
        int e = g * EPG + tid;
        if (dst[e] == n) {
            int p = atomicAdd(&cnt, 1);   // order irrelevant (sums)
            eidx[p] = e;
            esrc[p] = src[e];
        }
    }
    __syncthreads();
    const int deg = cnt;

    // phase 1: per-head softmax, one warp each (HEADS == 8 == warps)
    if (deg > 0) {
        float lm = -1e30f;
        for (int i = lane; i < deg; i += 32)
            lm = fmaxf(lm, g_logit[(size_t)eidx[i] * HEADS + wid]);
        #pragma unroll
        for (int o = 16; o > 0; o >>= 1) lm = fmaxf(lm, __shfl_xor_sync(0xFFFFFFFFu, lm, o));
        float ls = 0.f;
        for (int i = lane; i < deg; i += 32) {
            float ex = expf(g_logit[(size_t)eidx[i] * HEADS + wid] - lm);
            wsm[wid][i] = ex;
            ls += ex;
        }
        #pragma unroll
        for (int o = 16; o > 0; o >>= 1) ls += __shfl_xor_sync(0xFFFFFFFFu, ls, o);
        float inv = 1.f / ls;
        for (int i = lane; i < deg; i += 32) wsm[wid][i] *= inv;
    }
    __syncthreads();

    // attention mean over heads (write once per edge)
    if (tid < deg) {
        float s = 0.f;
        #pragma unroll
        for (int hh = 0; hh < HEADS; hh++) s += wsm[hh][tid];
        g_amean[eidx[tid]] = s * 0.125f;
    }

    // phase 2: h[n, :] = (1/8) sum_h sum_e w[h][e] * fs[src_e][h*768 + :]
    // thread owns half2 pair tid (dims 2tid..2tid+1); threads<128 also pair tid+256
    float2 a0 = make_float2(0.f, 0.f), a1 = make_float2(0.f, 0.f);
    for (int e = 0; e < deg; e++) {
        const __half2* fr = (const __half2*)(g_fsh + (size_t)esrc[e] * HO);
        #pragma unroll
        for (int hh = 0; hh < HEADS; hh++) {
            float we = wsm[hh][e];
            float2 v0 = __half22float2(fr[hh * 384 + tid]);
            a0.x = fmaf(we, v0.x, a0.x);
            a0.y = fmaf(we, v0.y, a0.y);
            if (tid < 128) {
                float2 v1 = __half22float2(fr[hh * 384 + 256 + tid]);
                a1.x = fmaf(we, v1.x, a1.x);
                a1.y = fmaf(we, v1.y, a1.y);
            }
        }
    }
    // write h (fp32) + fp16 image
    {
        size_t base = (size_t)n * NH;
        float2 o0 = make_float2(a0.x * 0.125f, a0.y * 0.125f);
        *(float2*)&g_h[base + 2 * tid] = o0;
        ((__half2*)(g_Af + base))[tid] = __floats2half2_rn(o0.x, o0.y);
        if (tid < 128) {
            float2 o1 = make_float2(a1.x * 0.125f, a1.y * 0.125f);
            *(float2*)&g_h[base + 512 + 2 * tid] = o1;
            ((__half2*)(g_Af + base))[256 + tid] = __floats2half2_rn(o1.x, o1.y);
        }
    }
}

// ---------------- attention gather to output ----------------
__global__ void attn_gather_k(const int* __restrict__ eids, float* __restrict__ out, int t)
{
    int i = blockIdx.x * 256 + threadIdx.x;
    if (i < BB * NATOM)
        out[(size_t)BB * NH + (size_t)t * BB * NATOM + i] = g_amean[eids[i]];
}

// ---------------- GRU projections: tiled fp32 GEMM ----------------
__global__ __launch_bounds__(256) void gru_gemm_k(
    const float* __restrict__ W_ih, const float* __restrict__ W_hh,
    const float* __restrict__ b_ih, const float* __restrict__ b_hh,
    const int* __restrict__ vnid)
{
    __shared__ float As[32][132];
    __shared__ float Bs[32][68];
    const int jb  = blockIdx.x * 64;        // 72 blocks
    const int sel = (jb >= H3) ? 1 : 0;
    const int j0  = sel ? jb - H3 : jb;
    const float* __restrict__ W    = sel ? W_hh : W_ih;
    const float* __restrict__ bias = sel ? b_hh : b_ih;
    float* __restrict__ Cout       = sel ? g_gh : g_gi;

    const int tid = threadIdx.x;
    const int ty = tid >> 4, tx = tid & 15;
    float acc[8][4];
    #pragma unroll
    for (int i = 0; i < 8; i++)
        #pragma unroll
        for (int j = 0; j < 4; j++) acc[i][j] = 0.f;

    for (int k0 = 0; k0 < NH; k0 += 32) {
        #pragma unroll
        for (int l = 0; l < 4; l++) {
            int f = tid * 4 + l;
            int r = f >> 3;
            int kv = (f & 7) * 4;
            const float* arow = sel ? (g_mol + (size_t)r * NH)
                                    : (g_h + (size_t)vnid[r] * NH);
            float4 v = *(const float4*)(arow + k0 + kv);
            As[kv + 0][r] = v.x; As[kv + 1][r] = v.y;
            As[kv + 2][r] = v.z; As[kv + 3][r] = v.w;
        }
        #pragma unroll
        for (int l = 0; l < 2; l++) {
            int f = tid * 2 + l;
            int c = f >> 3;
            int kv = (f & 7) * 4;
            float4 v = *(const float4*)(W + (size_t)(j0 + c) * NH + k0 + kv);
            Bs[kv + 0][c] = v.x; Bs[kv + 1][c] = v.y;
            Bs[kv + 2][c] = v.z; Bs[kv + 3][c] = v.w;
        }
        __syncthreads();
        #pragma unroll
        for (int k = 0; k < 32; k++) {
            float a[8], b[4];
            *(float4*)&a[0] = *(float4*)&As[k][ty * 8];
            *(float4*)&a[4] = *(float4*)&As[k][ty * 8 + 4];
            *(float4*)&b[0] = *(float4*)&Bs[k][tx * 4];
            #pragma unroll
            for (int i = 0; i < 8; i++)
                #pragma unroll
                for (int j = 0; j < 4; j++)
                    acc[i][j] = fmaf(a[i], b[j], acc[i][j]);
        }
        __syncthreads();
    }
    #pragma unroll
    for (int i = 0; i < 8; i++) {
        int b = ty * 8 + i;
        #pragma unroll
        for (int j = 0; j < 4; j++) {
            int jj = j0 + tx * 4 + j;
            Cout[(size_t)b * H3 + jj] = acc[i][j] + bias[jj];
        }
    }
}

// ---------------- GRU combine + relu ----------------
__global__ void gru_combine_k(float* __restrict__ out_mol, int write_out)
{
    int i = blockIdx.x * 256 + threadIdx.x;
    int b = i / NH, k = i % NH;
    size_t base = (size_t)b * H3;
    float ir = g_gi[base + k], iz = g_gi[base + NH + k], in_ = g_gi[base + 2 * NH + k];
    float hr = g_gh[base + k], hz = g_gh[base + NH + k], hn  = g_gh[base + 2 * NH + k];
    float r  = 1.f / (1.f + expf(-(ir + hr)));
    float z  = 1.f / (1.f + expf(-(iz + hz)));
    float nn = tanhf(in_ + r * hn);
    float hprev = g_mol[i];
    float hnew  = (1.f - z) * nn + z * hprev;
    hnew = fmaxf(hnew, 0.f);
    g_mol[i] = hnew;
    if (write_out) out_mol[i] = hnew;
}

// ---------------- launch ----------------
extern "C" void kernel_launch(void* const* d_in, const int* in_sizes, int n_in,
                              void* d_out, int out_size)
{
    const float* h_nodes  = (const float*)d_in[0];
    const float* mol_feat = (const float*)d_in[1];
    const float* W_src    = (const float*)d_in[2];
    const float* b_src    = (const float*)d_in[3];
    const float* W_dst    = (const float*)d_in[4];
    const float* b_dst    = (const float*)d_in[5];
    const float* attn_a   = (const float*)d_in[6];
    const float* W_ih     = (const float*)d_in[7];
    const float* W_hh     = (const float*)d_in[8];
    const float* b_ih     = (const float*)d_in[9];
    const float* b_hh     = (const float*)d_in[10];
    const int*   src      = (const int*)d_in[11];
    const int*   dst      = (const int*)d_in[12];
    const int*   vnid     = (const int*)d_in[13];
    const int*   eids     = (const int*)d_in[14];
    float* out = (float*)d_out;

    cudaFuncSetAttribute(gemm_mma, cudaFuncAttributeMaxDynamicSharedMemorySize, GEMM_SMEM);

    {
        long tot = (long)NN * NH + (long)BB * NH;
        init_k<<<(int)((tot + 255) / 256), 256>>>(h_nodes, mol_feat);
    }
    {
        dim3 gr(HO / 32, NH / 32, 6);
        transpose_conv_k<<<gr, dim3(32, 8)>>>(W_src, W_dst);
    }
    conv_attn_k<<<(TSTEP * HEADS * NH + 255) / 256, 256>>>(attn_a);

    __half* pBf = nullptr;
    cudaGetSymbolAddress((void**)&pBf, g_Bf);
    __half* pAh = nullptr;
    cudaGetSymbolAddress((void**)&pAh, g_ah);

    for (int t = 0; t < TSTEP; t++) {
        dim3 gg(HO / 128, NN / 128, 2);   // (48, 49, 2)
        size_t msz = (size_t)HO * NH;
        gemm_mma<<<gg, 256, GEMM_SMEM>>>(pBf + (size_t)(t * 2) * msz,
                                         b_src + (size_t)t * HO,
                                         b_dst + (size_t)t * HO);
        edge_logits_k<<<EE, 256>>>(src, dst, pAh + (size_t)t * HEADS * NH);
        node_aggregate_k<<<NN, 256>>>(src, dst);
        attn_gather_k<<<(BB * NATOM + 255) / 256, 256>>>(eids, out, t);
        gru_gemm_k<<<(H3 * 2) / 64, 256>>>(W_ih + (size_t)t * H3 * NH,
                                           W_hh + (size_t)t * H3 * NH,
                                           b_ih + (size_t)t * H3,
                                           b_hh + (size_t)t * H3, vnid);
        gru_combine_k<<<BB * NH / 256, 256>>>(out, t == TSTEP - 1);
    }
}

// round 13
// speedup vs baseline: 1.4659x; 1.1457x over previous
#include <cuda_runtime.h>
#include <cuda_bf16.h>
#include <cuda_fp16.h>
#include <math.h>
#include <stdint.h>

// ---------------- problem constants ----------------
#define NH    768            // H
#define HEADS 8
#define HO    6144           // HEADS*H
#define TSTEP 3
#define BB    128            // molecules
#define NATOM 48
#define NPG   49             // nodes per graph
#define EPG   144            // edges per graph
#define EINTRA 96
#define NN    6272           // B*NPG nodes
#define EE    18432          // B*EPG edges
#define H3    2304           // 3*H

// ---------------- device scratch (no allocation allowed) ----------------
__device__ float  g_h   [(size_t)NN * NH];    // node features fp32 (only virtual rows maintained)
__device__ __half g_fsh [(size_t)NN * HO];    // feat_src  [N, heads*H] fp16
__device__ __half g_fdh [(size_t)NN * HO];    // feat_dst  [N, heads*H] fp16
__device__ __half g_fdv [(size_t)BB * HO];    // feat_dst for virtual nodes only (t=2)
__device__ float  g_logit[(size_t)EE * HEADS];
__device__ float  g_mol [(size_t)BB * NH];
__device__ float  g_gi  [(size_t)BB * H3];
__device__ float  g_gh  [(size_t)BB * H3];

// fp16 operands for tensor-core GEMM
__device__ __half g_Af [(size_t)NN * NH];     // A in fp16
__device__ __half g_Afv[(size_t)BB * NH];     // compact virtual rows of A (fp16)
__device__ __half g_Bf [(size_t)6 * HO * NH]; // 6 weight mats, [N=6144,K=768] fp16
__device__ __half g_ah [(size_t)TSTEP * HEADS * NH];   // attn_a in fp16

// ---------------- init ----------------
__global__ void init_k(const float* __restrict__ h_nodes, const float* __restrict__ mol)
{
    long i = (long)blockIdx.x * 256 + threadIdx.x;
    const long tot = (long)NN * NH;
    if (i < tot) {
        g_Af[i] = __float2half_rn(h_nodes[i]);
    } else if (i < tot + (long)BB * NH) {
        g_mol[i - tot] = mol[i - tot];
    }
}

// ---------------- attn_a -> fp16 ----------------
__global__ void conv_attn_k(const float* __restrict__ attn_a)
{
    int i = blockIdx.x * 256 + threadIdx.x;
    if (i < TSTEP * HEADS * NH) g_ah[i] = __float2half_rn(attn_a[i]);
}

// ---------------- transpose + fp16-convert weight matrices ----------------
__global__ void transpose_conv_k(const float* __restrict__ Wsrc, const float* __restrict__ Wdst)
{
    const int mat = blockIdx.z;                    // t*2 + sel
    const float* W = ((mat & 1) ? Wdst : Wsrc) + (size_t)(mat >> 1) * NH * HO;
    __shared__ float tile[32][33];
    const int n0 = blockIdx.x * 32, k0 = blockIdx.y * 32;
    const int tx = threadIdx.x, ty = threadIdx.y;  // 32 x 8
    #pragma unroll
    for (int i = ty; i < 32; i += 8)
        tile[i][tx] = W[(size_t)(k0 + i) * HO + n0 + tx];
    __syncthreads();
    const size_t base = (size_t)mat * HO * NH;
    #pragma unroll
    for (int i = ty; i < 32; i += 8)
        g_Bf[base + (size_t)(n0 + i) * NH + k0 + tx] = __float2half_rn(tile[tx][i]);
}

// ================= mma.sync fp16 GEMM (R10/R12 proven config) ==========
// C = A * B^T, fp16 in / fp32 accum. Block tile 128x128, K-chunk 32,
// 6-stage cp.async pipeline, 8 warps (4m x 2n). blockIdx.z selects 0/1.

#define KC      32
#define ST_AF   0
#define ST_BF   8192
#define ST_SZ   16384
#define NSTAGE  6
#define GEMM_SMEM (NSTAGE * ST_SZ)         // 96 KB

__device__ __forceinline__ void cp16(uint32_t saddr, const void* gaddr) {
    asm volatile("cp.async.cg.shared.global [%0], [%1], 16;" :: "r"(saddr), "l"(gaddr) : "memory");
}
__device__ __forceinline__ void cp_commit() { asm volatile("cp.async.commit_group;" ::: "memory"); }
template <int N> __device__ __forceinline__ void cp_wait() {
    asm volatile("cp.async.wait_group %0;" :: "n"(N) : "memory");
}
__device__ __forceinline__ void ldsm4(uint32_t r[4], uint32_t addr) {
    asm volatile("ldmatrix.sync.aligned.m8n8.x4.shared.b16 {%0,%1,%2,%3}, [%4];"
        : "=r"(r[0]), "=r"(r[1]), "=r"(r[2]), "=r"(r[3]) : "r"(addr));
}
__device__ __forceinline__ void mma_f16(float c[4], const uint32_t a[4], const uint32_t b[2]) {
    asm volatile("mma.sync.aligned.m16n8k16.row.col.f32.f16.f16.f32 "
        "{%0,%1,%2,%3}, {%4,%5,%6,%7}, {%8,%9}, {%0,%1,%2,%3};"
        : "+f"(c[0]), "+f"(c[1]), "+f"(c[2]), "+f"(c[3])
        : "r"(a[0]), "r"(a[1]), "r"(a[2]), "r"(a[3]), "r"(b[0]), "r"(b[1]));
}
__device__ __forceinline__ uint32_t smem_u32(const void* p) {
    uint32_t a;
    asm("{ .reg .u64 t; cvta.to.shared.u64 t, %1; cvt.u32.u64 %0, t; }" : "=r"(a) : "l"(p));
    return a;
}

__global__ __launch_bounds__(256, 2) void gemm_mma(
    const __half* __restrict__ A,
    const __half* __restrict__ Bf_base,
    const float* __restrict__ bias0, const float* __restrict__ bias1,
    __half* __restrict__ C0, __half* __restrict__ C1)
{
    extern __shared__ char sm[];
    const uint32_t sb = smem_u32(sm);
    const int tid  = threadIdx.x;
    const int wid  = tid >> 5, lane = tid & 31;
    const int m0   = blockIdx.y * 128, n0 = blockIdx.x * 128;
    const int sel  = blockIdx.z;
    const size_t msz = (size_t)HO * NH;
    const __half* __restrict__ Bf = Bf_base + (size_t)sel * msz;
    const float* __restrict__ bias = sel ? bias1 : bias0;
    __half* __restrict__ C = sel ? C1 : C0;
    const int wm   = wid & 3;
    const int wn   = wid >> 2;

    const int seg0 = tid * 2;
    const int r0l  = seg0 >> 2,  c0l = seg0 & 3;
    const int r1l  = (seg0 + 1) >> 2, c1l = (seg0 + 1) & 3;
    const uint32_t so0 = r0l * 64 + ((c0l ^ (r0l & 3)) << 4);
    const uint32_t so1 = r1l * 64 + ((c1l ^ (r1l & 3)) << 4);

    #define LOAD_STAGE(stg, k0) do {                                              \
        uint32_t _b = sb + (stg) * ST_SZ;                                         \
        size_t ga0 = (size_t)(m0 + r0l) * NH + (k0) + c0l * 8;                    \
        size_t ga1 = (size_t)(m0 + r1l) * NH + (k0) + c1l * 8;                    \
        size_t gb0 = (size_t)(n0 + r0l) * NH + (k0) + c0l * 8;                    \
        size_t gb1 = (size_t)(n0 + r1l) * NH + (k0) + c1l * 8;                    \
        cp16(_b + ST_AF + so0, A + ga0);                                          \
        cp16(_b + ST_AF + so1, A + ga1);                                          \
        cp16(_b + ST_BF + so0, Bf + gb0);                                         \
        cp16(_b + ST_BF + so1, Bf + gb1);                                         \
    } while (0)

    const int sub = lane >> 3, rin = lane & 7;
    const int aRow0 = wm * 32 + (sub & 1) * 8 + rin;
    const int aSegB = sub >> 1;
    const int bRow0 = wn * 64 + (sub >> 1) * 8 + rin;
    const int bSegB = sub & 1;

    float acc[16][4];
    #pragma unroll
    for (int i = 0; i < 16; i++)
        #pragma unroll
        for (int j = 0; j < 4; j++) acc[i][j] = 0.f;

    #pragma unroll
    for (int s = 0; s < NSTAGE - 1; s++) {
        LOAD_STAGE(s, s * KC);
        cp_commit();
    }

    const int NCH = NH / KC;   // 24
    int stg = 0;
    for (int kc = 0; kc < NCH; kc++) {
        cp_wait<NSTAGE - 2>();
        __syncthreads();
        if (kc + NSTAGE - 1 < NCH) {
            LOAD_STAGE((kc + NSTAGE - 1) % NSTAGE, (kc + NSTAGE - 1) * KC);
        }
        cp_commit();

        const uint32_t stb = sb + stg * ST_SZ;
        #pragma unroll
        for (int k16 = 0; k16 < 2; k16++) {
            const int ks = k16 * 2;
            uint32_t aF[2][4], bb[8][2];
            #pragma unroll
            for (int mf = 0; mf < 2; mf++) {
                int row = aRow0 + mf * 16;
                uint32_t off = row * 64 + (((ks + aSegB) ^ (row & 3)) << 4);
                ldsm4(aF[mf], stb + ST_AF + off);
            }
            #pragma unroll
            for (int pp = 0; pp < 4; pp++) {
                int row = bRow0 + pp * 16;
                uint32_t off = row * 64 + (((ks + bSegB) ^ (row & 3)) << 4);
                uint32_t t[4];
                ldsm4(t, stb + ST_BF + off);
                bb[pp * 2][0] = t[0]; bb[pp * 2][1] = t[1];
                bb[pp * 2 + 1][0] = t[2]; bb[pp * 2 + 1][1] = t[3];
            }
            #pragma unroll
            for (int mf = 0; mf < 2; mf++)
                #pragma unroll
                for (int p = 0; p < 8; p++) mma_f16(acc[mf * 8 + p], aF[mf], bb[p]);
        }
        stg = (stg + 1 == NSTAGE) ? 0 : stg + 1;
    }

    const int qrow = lane >> 2, qcol = (lane & 3) * 2;
    const int gmb = m0 + wm * 32;
    const int gnb = n0 + wn * 64;
    #pragma unroll
    for (int mf = 0; mf < 2; mf++) {
        int r0 = gmb + mf * 16 + qrow;
        #pragma unroll
        for (int p = 0; p < 8; p++) {
            int cn = gnb + p * 8 + qcol;
            float bx = bias[cn], by = bias[cn + 1];
            __half2 v0 = __floats2half2_rn(acc[mf * 8 + p][0] + bx, acc[mf * 8 + p][1] + by);
            __half2 v1 = __floats2half2_rn(acc[mf * 8 + p][2] + bx, acc[mf * 8 + p][3] + by);
            *(__half2*)&C[(size_t)r0 * HO + cn] = v0;
            *(__half2*)&C[(size_t)(r0 + 8) * HO + cn] = v1;
        }
    }
    #undef LOAD_STAGE
}

// ---------------- edge logits (all edges): per (edge, head) warp ----------------
__global__ void edge_logits_k(const int* __restrict__ src, const int* __restrict__ dst,
                              const __half* __restrict__ aa_t)
{
    const int e = blockIdx.x;
    const int w = threadIdx.x >> 5, lane = threadIdx.x & 31;
    const int s = src[e], d = dst[e];
    const uint4* fsr = (const uint4*)(g_fsh + (size_t)s * HO + w * NH);
    const uint4* fdr = (const uint4*)(g_fdh + (size_t)d * HO + w * NH);
    const uint4* aar = (const uint4*)(aa_t + (size_t)w * NH);
    const __half2 hz  = __float2half2_rn(0.f);
    const __half2 hsl = __float2half2_rn(0.2f);
    float acc = 0.f;
    #pragma unroll
    for (int it = 0; it < 3; it++) {
        int idx = it * 32 + lane;
        uint4 Av = fsr[idx], D = fdr[idx], V = aar[idx];
        const __half2* hA = (const __half2*)&Av;
        const __half2* hD = (const __half2*)&D;
        const __half2* hV = (const __half2*)&V;
        #pragma unroll
        for (int j = 0; j < 4; j++) {
            __half2 x  = __hadd2(hA[j], hD[j]);
            __half2 lk = __hfma2(__hmin2(x, hz), hsl, __hmax2(x, hz));
            float2 f = __half22float2(__hmul2(lk, hV[j]));
            acc += f.x + f.y;
        }
    }
    #pragma unroll
    for (int o = 16; o > 0; o >>= 1) acc += __shfl_xor_sync(0xFFFFFFFFu, acc, o);
    if (lane == 0) g_logit[(size_t)e * HEADS + w] = acc;
}

// ---------------- edge logits (virtual edges only, t=2) ----------------
__global__ void edge_logits_virt_k(const int* __restrict__ src, const __half* __restrict__ aa_t)
{
    const int el = blockIdx.x;                 // 0..B*NATOM-1
    const int g  = el / NATOM;
    const int eg = g * EPG + EINTRA + (el % NATOM);
    const int w = threadIdx.x >> 5, lane = threadIdx.x & 31;
    const int s = src[eg];
    const uint4* fsr = (const uint4*)(g_fsh + (size_t)s * HO + w * NH);
    const uint4* fdr = (const uint4*)(g_fdv + (size_t)g * HO + w * NH);
    const uint4* aar = (const uint4*)(aa_t + (size_t)w * NH);
    const __half2 hz  = __float2half2_rn(0.f);
    const __half2 hsl = __float2half2_rn(0.2f);
    float acc = 0.f;
    #pragma unroll
    for (int it = 0; it < 3; it++) {
        int idx = it * 32 + lane;
        uint4 Av = fsr[idx], D = fdr[idx], V = aar[idx];
        const __half2* hA = (const __half2*)&Av;
        const __half2* hD = (const __half2*)&D;
        const __half2* hV = (const __half2*)&V;
        #pragma unroll
        for (int j = 0; j < 4; j++) {
            __half2 x  = __hadd2(hA[j], hD[j]);
            __half2 lk = __hfma2(__hmin2(x, hz), hsl, __hmax2(x, hz));
            float2 f = __half22float2(__hmul2(lk, hV[j]));
            acc += f.x + f.y;
        }
    }
    #pragma unroll
    for (int o = 16; o > 0; o >>= 1) acc += __shfl_xor_sync(0xFFFFFFFFu, acc, o);
    if (lane == 0) g_logit[(size_t)eg * HEADS + w] = acc;
}

// ---------------- per-node softmax + aggregation (full, t<2) ----------------
__global__ __launch_bounds__(256) void node_aggregate_k(
    const int* __restrict__ src, const int* __restrict__ dst,
    float* __restrict__ out, int t)
{
    const int n = blockIdx.x;
    const int tid = threadIdx.x;
    const int wid = tid >> 5, lane = tid & 31;
    __shared__ int   cnt;
    __shared__ int   eidx[EPG];
    __shared__ int   esrc[EPG];
    __shared__ float wsm[HEADS][EPG];

    const int g = n / NPG;
    const bool isv = (n - g * NPG) == NATOM;
    if (tid == 0) cnt = 0;
    __syncthreads();
    if (tid < EPG) {
        int e = g * EPG + tid;
        if (dst[e] == n) {
            int p = atomicAdd(&cnt, 1);
            eidx[p] = e;
            esrc[p] = src[e];
        }
    }
    __syncthreads();
    const int deg = cnt;

    if (deg > 0) {
        float lm = -1e30f;
        for (int i = lane; i < deg; i += 32)
            lm = fmaxf(lm, g_logit[(size_t)eidx[i] * HEADS + wid]);
        #pragma unroll
        for (int o = 16; o > 0; o >>= 1) lm = fmaxf(lm, __shfl_xor_sync(0xFFFFFFFFu, lm, o));
        float ls = 0.f;
        for (int i = lane; i < deg; i += 32) {
            float ex = expf(g_logit[(size_t)eidx[i] * HEADS + wid] - lm);
            wsm[wid][i] = ex;
            ls += ex;
        }
        #pragma unroll
        for (int o = 16; o > 0; o >>= 1) ls += __shfl_xor_sync(0xFFFFFFFFu, ls, o);
        float inv = 1.f / ls;
        for (int i = lane; i < deg; i += 32) wsm[wid][i] *= inv;
    }
    __syncthreads();

    // attention mean -> direct output (virtual nodes only; their edges are the attn edges)
    if (isv && tid < deg) {
        float s = 0.f;
        #pragma unroll
        for (int hh = 0; hh < HEADS; hh++) s += wsm[hh][tid];
        int j = eidx[tid] - g * EPG - EINTRA;   // 0..47
        out[(size_t)BB * NH + (size_t)t * BB * NATOM + g * NATOM + j] = s * 0.125f;
    }

    // feature aggregation
    float2 a0 = make_float2(0.f, 0.f), a1 = make_float2(0.f, 0.f);
    for (int e = 0; e < deg; e++) {
        const __half2* fr = (const __half2*)(g_fsh + (size_t)esrc[e] * HO);
        #pragma unroll
        for (int hh = 0; hh < HEADS; hh++) {
            float we = wsm[hh][e];
            float2 v0 = __half22float2(fr[hh * 384 + tid]);
            a0.x = fmaf(we, v0.x, a0.x);
            a0.y = fmaf(we, v0.y, a0.y);
            if (tid < 128) {
                float2 v1 = __half22float2(fr[hh * 384 + 256 + tid]);
                a1.x = fmaf(we, v1.x, a1.x);
                a1.y = fmaf(we, v1.y, a1.y);
            }
        }
    }
    {
        size_t base = (size_t)n * NH;
        float2 o0 = make_float2(a0.x * 0.125f, a0.y * 0.125f);
        __half2 h0 = __floats2half2_rn(o0.x, o0.y);
        ((__half2*)(g_Af + base))[tid] = h0;
        if (isv) {
            *(float2*)&g_h[base + 2 * tid] = o0;
            ((__half2*)(g_Afv + (size_t)g * NH))[tid] = h0;
        }
        if (tid < 128) {
            float2 o1 = make_float2(a1.x * 0.125f, a1.y * 0.125f);
            __half2 h1 = __floats2half2_rn(o1.x, o1.y);
            ((__half2*)(g_Af + base))[256 + tid] = h1;
            if (isv) {
                *(float2*)&g_h[base + 512 + 2 * tid] = o1;
                ((__half2*)(g_Afv + (size_t)g * NH))[256 + tid] = h1;
            }
        }
    }
}

// ---------------- virtual-only softmax + aggregation (t=2) ----------------
// Block g: its virtual node's in-edges are exactly edges g*EPG+96 .. +143.
__global__ __launch_bounds__(256) void node_aggregate_virt_k(
    const int* __restrict__ src, float* __restrict__ out, int t)
{
    const int g = blockIdx.x;
    const int tid = threadIdx.x;
    const int wid = tid >> 5, lane = tid & 31;
    __shared__ int   esrc[NATOM];
    __shared__ float wsm[HEADS][NATOM];

    if (tid < NATOM) esrc[tid] = src[g * EPG + EINTRA + tid];

    // warp wid = head wid softmax over 48 logits
    {
        float lm = -1e30f;
        for (int i = lane; i < NATOM; i += 32)
            lm = fmaxf(lm, g_logit[(size_t)(g * EPG + EINTRA + i) * HEADS + wid]);
        #pragma unroll
        for (int o = 16; o > 0; o >>= 1) lm = fmaxf(lm, __shfl_xor_sync(0xFFFFFFFFu, lm, o));
        float ls = 0.f;
        for (int i = lane; i < NATOM; i += 32) {
            float ex = expf(g_logit[(size_t)(g * EPG + EINTRA + i) * HEADS + wid] - lm);
            wsm[wid][i] = ex;
            ls += ex;
        }
        #pragma unroll
        for (int o = 16; o > 0; o >>= 1) ls += __shfl_xor_sync(0xFFFFFFFFu, ls, o);
        float inv = 1.f / ls;
        for (int i = lane; i < NATOM; i += 32) wsm[wid][i] *= inv;
    }
    __syncthreads();

    if (tid < NATOM) {
        float s = 0.f;
        #pragma unroll
        for (int hh = 0; hh < HEADS; hh++) s += wsm[hh][tid];
        out[(size_t)BB * NH + (size_t)t * BB * NATOM + g * NATOM + tid] = s * 0.125f;
    }

    // aggregate features into h[vnid] (fp32 only; nothing downstream needs fp16)
    float2 a0 = make_float2(0.f, 0.f), a1 = make_float2(0.f, 0.f);
    for (int e = 0; e < NATOM; e++) {
        const __half2* fr = (const __half2*)(g_fsh + (size_t)esrc[e] * HO);
        #pragma unroll
        for (int hh = 0; hh < HEADS; hh++) {
            float we = wsm[hh][e];
            float2 v0 = __half22float2(fr[hh * 384 + tid]);
            a0.x = fmaf(we, v0.x, a0.x);
            a0.y = fmaf(we, v0.y, a0.y);
            if (tid < 128) {
                float2 v1 = __half22float2(fr[hh * 384 + 256 + tid]);
                a1.x = fmaf(we, v1.x, a1.x);
                a1.y = fmaf(we, v1.y, a1.y);
            }
        }
    }
    {
        size_t base = (size_t)(g * NPG + NATOM) * NH;
        *(float2*)&g_h[base + 2 * tid] = make_float2(a0.x * 0.125f, a0.y * 0.125f);
        if (tid < 128)
            *(float2*)&g_h[base + 512 + 2 * tid] = make_float2(a1.x * 0.125f, a1.y * 0.125f);
    }
}

// ---------------- GRU projections: tiled fp32 GEMM ----------------
__global__ __launch_bounds__(256) void gru_gemm_k(
    const float* __restrict__ W_ih, const float* __restrict__ W_hh,
    const float* __restrict__ b_ih, const float* __restrict__ b_hh,
    const int* __restrict__ vnid)
{
    __shared__ float As[32][132];
    __shared__ float Bs[32][68];
    const int jb  = blockIdx.x * 64;
    const int sel = (jb >= H3) ? 1 : 0;
    const int j0  = sel ? jb - H3 : jb;
    const float* __restrict__ W    = sel ? W_hh : W_ih;
    const float* __restrict__ bias = sel ? b_hh : b_ih;
    float* __restrict__ Cout       = sel ? g_gh : g_gi;

    const int tid = threadIdx.x;
    const int ty = tid >> 4, tx = tid & 15;
    float acc[8][4];
    #pragma unroll
    for (int i = 0; i < 8; i++)
        #pragma unroll
        for (int j = 0; j < 4; j++) acc[i][j] = 0.f;

    for (int k0 = 0; k0 < NH; k0 += 32) {
        #pragma unroll
        for (int l = 0; l < 4; l++) {
            int f = tid * 4 + l;
            int r = f >> 3;
            int kv = (f & 7) * 4;
            const float* arow = sel ? (g_mol + (size_t)r * NH)
                                    : (g_h + (size_t)vnid[r] * NH);
            float4 v = *(const float4*)(arow + k0 + kv);
            As[kv + 0][r] = v.x; As[kv + 1][r] = v.y;
            As[kv + 2][r] = v.z; As[kv + 3][r] = v.w;
        }
        #pragma unroll
        for (int l = 0; l < 2; l++) {
            int f = tid * 2 + l;
            int c = f >> 3;
            int kv = (f & 7) * 4;
            float4 v = *(const float4*)(W + (size_t)(j0 + c) * NH + k0 + kv);
            Bs[kv + 0][c] = v.x; Bs[kv + 1][c] = v.y;
            Bs[kv + 2][c] = v.z; Bs[kv + 3][c] = v.w;
        }
        __syncthreads();
        #pragma unroll
        for (int k = 0; k < 32; k++) {
            float a[8], b[4];
            *(float4*)&a[0] = *(float4*)&As[k][ty * 8];
            *(float4*)&a[4] = *(float4*)&As[k][ty * 8 + 4];
            *(float4*)&b[0] = *(float4*)&Bs[k][tx * 4];
            #pragma unroll
            for (int i = 0; i < 8; i++)
                #pragma unroll
                for (int j = 0; j < 4; j++)
                    acc[i][j] = fmaf(a[i], b[j], acc[i][j]);
        }
        __syncthreads();
    }
    #pragma unroll
    for (int i = 0; i < 8; i++) {
        int b = ty * 8 + i;
        #pragma unroll
        for (int j = 0; j < 4; j++) {
            int jj = j0 + tx * 4 + j;
            Cout[(size_t)b * H3 + jj] = acc[i][j] + bias[jj];
        }
    }
}

// ---------------- GRU combine + relu ----------------
__global__ void gru_combine_k(float* __restrict__ out_mol, int write_out)
{
    int i = blockIdx.x * 256 + threadIdx.x;
    int b = i / NH, k = i % NH;
    size_t base = (size_t)b * H3;
    float ir = g_gi[base + k], iz = g_gi[base + NH + k], in_ = g_gi[base + 2 * NH + k];
    float hr = g_gh[base + k], hz = g_gh[base + NH + k], hn  = g_gh[base + 2 * NH + k];
    float r  = 1.f / (1.f + expf(-(ir + hr)));
    float z  = 1.f / (1.f + expf(-(iz + hz)));
    float nn = tanhf(in_ + r * hn);
    float hprev = g_mol[i];
    float hnew  = (1.f - z) * nn + z * hprev;
    hnew = fmaxf(hnew, 0.f);
    g_mol[i] = hnew;
    if (write_out) out_mol[i] = hnew;
}

// ---------------- launch ----------------
extern "C" void kernel_launch(void* const* d_in, const int* in_sizes, int n_in,
                              void* d_out, int out_size)
{
    const float* h_nodes  = (const float*)d_in[0];
    const float* mol_feat = (const float*)d_in[1];
    const float* W_src    = (const float*)d_in[2];
    const float* b_src    = (const float*)d_in[3];
    const float* W_dst    = (const float*)d_in[4];
    const float* b_dst    = (const float*)d_in[5];
    const float* attn_a   = (const float*)d_in[6];
    const float* W_ih     = (const float*)d_in[7];
    const float* W_hh     = (const float*)d_in[8];
    const float* b_ih     = (const float*)d_in[9];
    const float* b_hh     = (const float*)d_in[10];
    const int*   src      = (const int*)d_in[11];
    const int*   dst      = (const int*)d_in[12];
    const int*   vnid     = (const int*)d_in[13];
    float* out = (float*)d_out;

    cudaFuncSetAttribute(gemm_mma, cudaFuncAttributeMaxDynamicSharedMemorySize, GEMM_SMEM);

    {
        long tot = (long)NN * NH + (long)BB * NH;
        init_k<<<(int)((tot + 255) / 256), 256>>>(h_nodes, mol_feat);
    }
    {
        dim3 gr(HO / 32, NH / 32, 6);
        transpose_conv_k<<<gr, dim3(32, 8)>>>(W_src, W_dst);
    }
    conv_attn_k<<<(TSTEP * HEADS * NH + 255) / 256, 256>>>(attn_a);

    __half *pBf, *pAh, *pAf, *pAfv, *pFsh, *pFdh, *pFdv;
    cudaGetSymbolAddress((void**)&pBf, g_Bf);
    cudaGetSymbolAddress((void**)&pAh, g_ah);
    cudaGetSymbolAddress((void**)&pAf, g_Af);
    cudaGetSymbolAddress((void**)&pAfv, g_Afv);
    cudaGetSymbolAddress((void**)&pFsh, g_fsh);
    cudaGetSymbolAddress((void**)&pFdh, g_fdh);
    cudaGetSymbolAddress((void**)&pFdv, g_fdv);

    const size_t msz = (size_t)HO * NH;
    for (int t = 0; t < TSTEP; t++) {
        if (t < TSTEP - 1) {
            dim3 gg(HO / 128, NN / 128, 2);   // (48, 49, 2)
            gemm_mma<<<gg, 256, GEMM_SMEM>>>(pAf, pBf + (size_t)(t * 2) * msz,
                                             b_src + (size_t)t * HO,
                                             b_dst + (size_t)t * HO, pFsh, pFdh);
            edge_logits_k<<<EE, 256>>>(src, dst, pAh + (size_t)t * HEADS * NH);
            node_aggregate_k<<<NN, 256>>>(src, dst, out, t);
        } else {
            // fs: full (atom sources); fd: virtual rows only
            dim3 gg(HO / 128, NN / 128, 1);
            gemm_mma<<<gg, 256, GEMM_SMEM>>>(pAf, pBf + (size_t)(t * 2) * msz,
                                             b_src + (size_t)t * HO,
                                             b_src + (size_t)t * HO, pFsh, pFsh);
            dim3 gv(HO / 128, 1, 1);
            gemm_mma<<<gv, 256, GEMM_SMEM>>>(pAfv, pBf + (size_t)(t * 2 + 1) * msz,
                                             b_dst + (size_t)t * HO,
                                             b_dst + (size_t)t * HO, pFdv, pFdv);
            edge_logits_virt_k<<<BB * NATOM, 256>>>(src, pAh + (size_t)t * HEADS * NH);
            node_aggregate_virt_k<<<BB, 256>>>(src, out, t);
        }
        gru_gemm_k<<<(H3 * 2) / 64, 256>>>(W_ih + (size_t)t * H3 * NH,
                                           W_hh + (size_t)t * H3 * NH,
                                           b_ih + (size_t)t * H3,
                                           b_hh + (size_t)t * H3, vnid);
        gru_combine_k<<<BB * NH / 256, 256>>>(out, t == TSTEP - 1);
    }
}

// round 15
// speedup vs baseline: 1.4853x; 1.0132x over previous
#include <cuda_runtime.h>
#include <cuda_bf16.h>
#include <cuda_fp16.h>
#include <math.h>
#include <stdint.h>

// ---------------- problem constants ----------------
#define NH    768            // H
#define HEADS 8
#define HO    6144           // HEADS*H
#define TSTEP 3
#define BB    128            // molecules
#define NATOM 48
#define NPG   49             // nodes per graph
#define EPG   144            // edges per graph
#define EINTRA 96
#define NN    6272           // B*NPG nodes
#define EE    18432          // B*EPG edges
#define H3    2304           // 3*H

// ---------------- device scratch (no allocation allowed) ----------------
__device__ float  g_h   [(size_t)NN * NH];    // node features fp32 (only virtual rows maintained)
__device__ __half g_fsh [(size_t)NN * HO];    // feat_src  [N, heads*H] fp16
__device__ __half g_fdh [(size_t)NN * HO];    // feat_dst  [N, heads*H] fp16
__device__ __half g_fdv [(size_t)BB * HO];    // feat_dst for virtual nodes only (t=2)
__device__ float  g_mol [(size_t)BB * NH];
__device__ float  g_gi  [(size_t)BB * H3];
__device__ float  g_gh  [(size_t)BB * H3];

// fp16 operands for tensor-core GEMM
__device__ __half g_Af [(size_t)NN * NH];     // A in fp16
__device__ __half g_Afv[(size_t)BB * NH];     // compact virtual rows of A (fp16)
__device__ __half g_Bf [(size_t)6 * HO * NH]; // 6 weight mats, [N=6144,K=768] fp16
__device__ __half g_ah [(size_t)TSTEP * HEADS * NH];   // attn_a in fp16

// ---------------- init ----------------
__global__ void init_k(const float* __restrict__ h_nodes, const float* __restrict__ mol)
{
    long i = (long)blockIdx.x * 256 + threadIdx.x;
    const long tot = (long)NN * NH;
    if (i < tot) {
        g_Af[i] = __float2half_rn(h_nodes[i]);
    } else if (i < tot + (long)BB * NH) {
        g_mol[i - tot] = mol[i - tot];
    }
}

// ---------------- attn_a -> fp16 ----------------
__global__ void conv_attn_k(const float* __restrict__ attn_a)
{
    int i = blockIdx.x * 256 + threadIdx.x;
    if (i < TSTEP * HEADS * NH) g_ah[i] = __float2half_rn(attn_a[i]);
}

// ---------------- transpose + fp16-convert weight matrices ----------------
__global__ void transpose_conv_k(const float* __restrict__ Wsrc, const float* __restrict__ Wdst)
{
    const int mat = blockIdx.z;                    // t*2 + sel
    const float* W = ((mat & 1) ? Wdst : Wsrc) + (size_t)(mat >> 1) * NH * HO;
    __shared__ float tile[32][33];
    const int n0 = blockIdx.x * 32, k0 = blockIdx.y * 32;
    const int tx = threadIdx.x, ty = threadIdx.y;  // 32 x 8
    #pragma unroll
    for (int i = ty; i < 32; i += 8)
        tile[i][tx] = W[(size_t)(k0 + i) * HO + n0 + tx];
    __syncthreads();
    const size_t base = (size_t)mat * HO * NH;
    #pragma unroll
    for (int i = ty; i < 32; i += 8)
        g_Bf[base + (size_t)(n0 + i) * NH + k0 + tx] = __float2half_rn(tile[tx][i]);
}

// ================= mma.sync fp16 GEMM (proven config, untouched) ==========
#define KC      32
#define ST_AF   0
#define ST_BF   8192
#define ST_SZ   16384
#define NSTAGE  6
#define GEMM_SMEM (NSTAGE * ST_SZ)         // 96 KB

__device__ __forceinline__ void cp16(uint32_t saddr, const void* gaddr) {
    asm volatile("cp.async.cg.shared.global [%0], [%1], 16;" :: "r"(saddr), "l"(gaddr) : "memory");
}
__device__ __forceinline__ void cp_commit() { asm volatile("cp.async.commit_group;" ::: "memory"); }
template <int N> __device__ __forceinline__ void cp_wait() {
    asm volatile("cp.async.wait_group %0;" :: "n"(N) : "memory");
}
__device__ __forceinline__ void ldsm4(uint32_t r[4], uint32_t addr) {
    asm volatile("ldmatrix.sync.aligned.m8n8.x4.shared.b16 {%0,%1,%2,%3}, [%4];"
        : "=r"(r[0]), "=r"(r[1]), "=r"(r[2]), "=r"(r[3]) : "r"(addr));
}
__device__ __forceinline__ void mma_f16(float c[4], const uint32_t a[4], const uint32_t b[2]) {
    asm volatile("mma.sync.aligned.m16n8k16.row.col.f32.f16.f16.f32 "
        "{%0,%1,%2,%3}, {%4,%5,%6,%7}, {%8,%9}, {%0,%1,%2,%3};"
        : "+f"(c[0]), "+f"(c[1]), "+f"(c[2]), "+f"(c[3])
        : "r"(a[0]), "r"(a[1]), "r"(a[2]), "r"(a[3]), "r"(b[0]), "r"(b[1]));
}
__device__ __forceinline__ uint32_t smem_u32(const void* p) {
    uint32_t a;
    asm("{ .reg .u64 t; cvta.to.shared.u64 t, %1; cvt.u32.u64 %0, t; }" : "=r"(a) : "l"(p));
    return a;
}

__global__ __launch_bounds__(256, 2) void gemm_mma(
    const __half* __restrict__ A,
    const __half* __restrict__ Bf_base,
    const float* __restrict__ bias0, const float* __restrict__ bias1,
    __half* __restrict__ C0, __half* __restrict__ C1)
{
    extern __shared__ char sm[];
    const uint32_t sb = smem_u32(sm);
    const int tid  = threadIdx.x;
    const int wid  = tid >> 5, lane = tid & 31;
    const int m0   = blockIdx.y * 128, n0 = blockIdx.x * 128;
    const int sel  = blockIdx.z;
    const size_t msz = (size_t)HO * NH;
    const __half* __restrict__ Bf = Bf_base + (size_t)sel * msz;
    const float* __restrict__ bias = sel ? bias1 : bias0;
    __half* __restrict__ C = sel ? C1 : C0;
    const int wm   = wid & 3;
    const int wn   = wid >> 2;

    const int seg0 = tid * 2;
    const int r0l  = seg0 >> 2,  c0l = seg0 & 3;
    const int r1l  = (seg0 + 1) >> 2, c1l = (seg0 + 1) & 3;
    const uint32_t so0 = r0l * 64 + ((c0l ^ (r0l & 3)) << 4);
    const uint32_t so1 = r1l * 64 + ((c1l ^ (r1l & 3)) << 4);

    #define LOAD_STAGE(stg, k0) do {                                              \
        uint32_t _b = sb + (stg) * ST_SZ;                                         \
        size_t ga0 = (size_t)(m0 + r0l) * NH + (k0) + c0l * 8;                    \
        size_t ga1 = (size_t)(m0 + r1l) * NH + (k0) + c1l * 8;                    \
        size_t gb0 = (size_t)(n0 + r0l) * NH + (k0) + c0l * 8;                    \
        size_t gb1 = (size_t)(n0 + r1l) * NH + (k0) + c1l * 8;                    \
        cp16(_b + ST_AF + so0, A + ga0);                                          \
        cp16(_b + ST_AF + so1, A + ga1);                                          \
        cp16(_b + ST_BF + so0, Bf + gb0);                                         \
        cp16(_b + ST_BF + so1, Bf + gb1);                                         \
    } while (0)

    const int sub = lane >> 3, rin = lane & 7;
    const int aRow0 = wm * 32 + (sub & 1) * 8 + rin;
    const int aSegB = sub >> 1;
    const int bRow0 = wn * 64 + (sub >> 1) * 8 + rin;
    const int bSegB = sub & 1;

    float acc[16][4];
    #pragma unroll
    for (int i = 0; i < 16; i++)
        #pragma unroll
        for (int j = 0; j < 4; j++) acc[i][j] = 0.f;

    #pragma unroll
    for (int s = 0; s < NSTAGE - 1; s++) {
        LOAD_STAGE(s, s * KC);
        cp_commit();
    }

    const int NCH = NH / KC;   // 24
    int stg = 0;
    for (int kc = 0; kc < NCH; kc++) {
        cp_wait<NSTAGE - 2>();
        __syncthreads();
        if (kc + NSTAGE - 1 < NCH) {
            LOAD_STAGE((kc + NSTAGE - 1) % NSTAGE, (kc + NSTAGE - 1) * KC);
        }
        cp_commit();

        const uint32_t stb = sb + stg * ST_SZ;
        #pragma unroll
        for (int k16 = 0; k16 < 2; k16++) {
            const int ks = k16 * 2;
            uint32_t aF[2][4], bb[8][2];
            #pragma unroll
            for (int mf = 0; mf < 2; mf++) {
                int row = aRow0 + mf * 16;
                uint32_t off = row * 64 + (((ks + aSegB) ^ (row & 3)) << 4);
                ldsm4(aF[mf], stb + ST_AF + off);
            }
            #pragma unroll
            for (int pp = 0; pp < 4; pp++) {
                int row = bRow0 + pp * 16;
                uint32_t off = row * 64 + (((ks + bSegB) ^ (row & 3)) << 4);
                uint32_t t[4];
                ldsm4(t, stb + ST_BF + off);
                bb[pp * 2][0] = t[0]; bb[pp * 2][1] = t[1];
                bb[pp * 2 + 1][0] = t[2]; bb[pp * 2 + 1][1] = t[3];
            }
            #pragma unroll
            for (int mf = 0; mf < 2; mf++)
                #pragma unroll
                for (int p = 0; p < 8; p++) mma_f16(acc[mf * 8 + p], aF[mf], bb[p]);
        }
        stg = (stg + 1 == NSTAGE) ? 0 : stg + 1;
    }

    const int qrow = lane >> 2, qcol = (lane & 3) * 2;
    const int gmb = m0 + wm * 32;
    const int gnb = n0 + wn * 64;
    #pragma unroll
    for (int mf = 0; mf < 2; mf++) {
        int r0 = gmb + mf * 16 + qrow;
        #pragma unroll
        for (int p = 0; p < 8; p++) {
            int cn = gnb + p * 8 + qcol;
            float bx = bias[cn], by = bias[cn + 1];
            __half2 v0 = __floats2half2_rn(acc[mf * 8 + p][0] + bx, acc[mf * 8 + p][1] + by);
            __half2 v1 = __floats2half2_rn(acc[mf * 8 + p][2] + bx, acc[mf * 8 + p][3] + by);
            *(__half2*)&C[(size_t)r0 * HO + cn] = v0;
            *(__half2*)&C[(size_t)(r0 + 8) * HO + cn] = v1;
        }
    }
    #undef LOAD_STAGE
}

// ---- shared logit helper: warp-segment dot with fd/aa in smem ----
__device__ __forceinline__ float logit_seg(const uint4* __restrict__ fs4,
                                           const uint4* __restrict__ fd4,
                                           const uint4* __restrict__ aa4,
                                           int lane)
{
    const __half2 hz  = __float2half2_rn(0.f);
    const __half2 hsl = __float2half2_rn(0.2f);
    float acc = 0.f;
    #pragma unroll
    for (int it = 0; it < 3; it++) {
        int idx = it * 32 + lane;
        uint4 Av = fs4[idx], D = fd4[idx], V = aa4[idx];
        const __half2* hA = (const __half2*)&Av;
        const __half2* hD = (const __half2*)&D;
        const __half2* hV = (const __half2*)&V;
        #pragma unroll
        for (int j = 0; j < 4; j++) {
            __half2 x  = __hadd2(hA[j], hD[j]);
            __half2 lk = __hfma2(__hmin2(x, hz), hsl, __hmax2(x, hz));
            float2 f = __half22float2(__hmul2(lk, hV[j]));
            acc += f.x + f.y;
        }
    }
    #pragma unroll
    for (int o = 16; o > 0; o >>= 1) acc += __shfl_xor_sync(0xFFFFFFFFu, acc, o);
    return acc;
}

// ---------------- FUSED: logits + softmax + aggregation (t<2) ----------------
__global__ __launch_bounds__(256) void node_aggregate_fused_k(
    const int* __restrict__ src, const int* __restrict__ dst,
    const __half* __restrict__ aa_t, float* __restrict__ out, int t)
{
    const int n = blockIdx.x;
    const int tid = threadIdx.x;
    const int wid = tid >> 5, lane = tid & 31;
    __shared__ int    cnt;
    __shared__ int    eidx[EPG];
    __shared__ int    esrc[EPG];
    __shared__ float  wsm[HEADS][EPG];
    __shared__ __align__(16) __half fd_s[HO];
    __shared__ __align__(16) __half aa_s[HO];

    const int g = n / NPG;
    const bool isv = (n - g * NPG) == NATOM;
    if (tid == 0) cnt = 0;
    // stage fd[n] and attn_a into smem (768 uint4 each)
    {
        const uint4* fdg = (const uint4*)(g_fdh + (size_t)n * HO);
        const uint4* aag = (const uint4*)aa_t;
        uint4* fds = (uint4*)fd_s;
        uint4* aas = (uint4*)aa_s;
        #pragma unroll
        for (int i = 0; i < 3; i++) {
            fds[tid + 256 * i] = fdg[tid + 256 * i];
            aas[tid + 256 * i] = aag[tid + 256 * i];
        }
    }
    __syncthreads();
    if (tid < EPG) {
        int e = g * EPG + tid;
        if (dst[e] == n) {
            int p = atomicAdd(&cnt, 1);
            eidx[p] = e;
            esrc[p] = src[e];
        }
    }
    __syncthreads();
    const int deg = cnt;

    // logits: warp wid = head wid
    const uint4* fd4 = ((const uint4*)fd_s) + wid * 96;
    const uint4* aa4 = ((const uint4*)aa_s) + wid * 96;
    for (int e = 0; e < deg; e++) {
        const uint4* fs4 = ((const uint4*)(g_fsh + (size_t)esrc[e] * HO)) + wid * 96;
        float lg = logit_seg(fs4, fd4, aa4, lane);
        if (lane == 0) wsm[wid][e] = lg;
    }
    __syncwarp();

    // warp-local softmax
    if (deg > 0) {
        float lm = -1e30f;
        for (int i = lane; i < deg; i += 32) lm = fmaxf(lm, wsm[wid][i]);
        #pragma unroll
        for (int o = 16; o > 0; o >>= 1) lm = fmaxf(lm, __shfl_xor_sync(0xFFFFFFFFu, lm, o));
        float ls = 0.f;
        for (int i = lane; i < deg; i += 32) {
            float ex = expf(wsm[wid][i] - lm);
            wsm[wid][i] = ex;
            ls += ex;
        }
        #pragma unroll
        for (int o = 16; o > 0; o >>= 1) ls += __shfl_xor_sync(0xFFFFFFFFu, ls, o);
        float inv = 1.f / ls;
        for (int i = lane; i < deg; i += 32) wsm[wid][i] *= inv;
    }
    __syncthreads();

    // attention mean -> direct output (virtual nodes only)
    if (isv && tid < deg) {
        float s = 0.f;
        #pragma unroll
        for (int hh = 0; hh < HEADS; hh++) s += wsm[hh][tid];
        int j = eidx[tid] - g * EPG - EINTRA;   // 0..47
        out[(size_t)BB * NH + (size_t)t * BB * NATOM + g * NATOM + j] = s * 0.125f;
    }

    // feature aggregation (fs rows are L2-hot from the logit pass)
    float2 a0 = make_float2(0.f, 0.f), a1 = make_float2(0.f, 0.f);
    for (int e = 0; e < deg; e++) {
        const __half2* fr = (const __half2*)(g_fsh + (size_t)esrc[e] * HO);
        #pragma unroll
        for (int hh = 0; hh < HEADS; hh++) {
            float we = wsm[hh][e];
            float2 v0 = __half22float2(fr[hh * 384 + tid]);
            a0.x = fmaf(we, v0.x, a0.x);
            a0.y = fmaf(we, v0.y, a0.y);
            if (tid < 128) {
                float2 v1 = __half22float2(fr[hh * 384 + 256 + tid]);
                a1.x = fmaf(we, v1.x, a1.x);
                a1.y = fmaf(we, v1.y, a1.y);
            }
        }
    }
    {
        size_t base = (size_t)n * NH;
        float2 o0 = make_float2(a0.x * 0.125f, a0.y * 0.125f);
        __half2 h0 = __floats2half2_rn(o0.x, o0.y);
        ((__half2*)(g_Af + base))[tid] = h0;
        if (isv) {
            *(float2*)&g_h[base + 2 * tid] = o0;
            ((__half2*)(g_Afv + (size_t)g * NH))[tid] = h0;
        }
        if (tid < 128) {
            float2 o1 = make_float2(a1.x * 0.125f, a1.y * 0.125f);
            __half2 h1 = __floats2half2_rn(o1.x, o1.y);
            ((__half2*)(g_Af + base))[256 + tid] = h1;
            if (isv) {
                *(float2*)&g_h[base + 512 + 2 * tid] = o1;
                ((__half2*)(g_Afv + (size_t)g * NH))[256 + tid] = h1;
            }
        }
    }
}

// ---------------- FUSED virtual-only path (t=2) ----------------
__global__ __launch_bounds__(256) void node_aggregate_virt_fused_k(
    const int* __restrict__ src, const __half* __restrict__ aa_t,
    float* __restrict__ out, int t)
{
    const int g = blockIdx.x;
    const int tid = threadIdx.x;
    const int wid = tid >> 5, lane = tid & 31;
    __shared__ int    esrc[NATOM];
    __shared__ float  wsm[HEADS][NATOM];
    __shared__ __align__(16) __half fd_s[HO];
    __shared__ __align__(16) __half aa_s[HO];

    {
        const uint4* fdg = (const uint4*)(g_fdv + (size_t)g * HO);
        const uint4* aag = (const uint4*)aa_t;
        uint4* fds = (uint4*)fd_s;
        uint4* aas = (uint4*)aa_s;
        #pragma unroll
        for (int i = 0; i < 3; i++) {
            fds[tid + 256 * i] = fdg[tid + 256 * i];
            aas[tid + 256 * i] = aag[tid + 256 * i];
        }
    }
    if (tid < NATOM) esrc[tid] = src[g * EPG + EINTRA + tid];
    __syncthreads();

    const uint4* fd4 = ((const uint4*)fd_s) + wid * 96;
    const uint4* aa4 = ((const uint4*)aa_s) + wid * 96;
    for (int e = 0; e < NATOM; e++) {
        const uint4* fs4 = ((const uint4*)(g_fsh + (size_t)esrc[e] * HO)) + wid * 96;
        float lg = logit_seg(fs4, fd4, aa4, lane);
        if (lane == 0) wsm[wid][e] = lg;
    }
    __syncwarp();

    // warp-local softmax over 48
    {
        float lm = -1e30f;
        for (int i = lane; i < NATOM; i += 32) lm = fmaxf(lm, wsm[wid][i]);
        #pragma unroll
        for (int o = 16; o > 0; o >>= 1) lm = fmaxf(lm, __shfl_xor_sync(0xFFFFFFFFu, lm, o));
        float ls = 0.f;
        for (int i = lane; i < NATOM; i += 32) {
            float ex = expf(wsm[wid][i] - lm);
            wsm[wid][i] = ex;
            ls += ex;
        }
        #pragma unroll
        for (int o = 16; o > 0; o >>= 1) ls += __shfl_xor_sync(0xFFFFFFFFu, ls, o);
        float inv = 1.f / ls;
        for (int i = lane; i < NATOM; i += 32) wsm[wid][i] *= inv;
    }
    __syncthreads();

    if (tid < NATOM) {
        float s = 0.f;
        #pragma unroll
        for (int hh = 0; hh < HEADS; hh++) s += wsm[hh][tid];
        out[(size_t)BB * NH + (size_t)t * BB * NATOM + g * NATOM + tid] = s * 0.125f;
    }

    float2 a0 = make_float2(0.f, 0.f), a1 = make_float2(0.f, 0.f);
    for (int e = 0; e < NATOM; e++) {
        const __half2* fr = (const __half2*)(g_fsh + (size_t)esrc[e] * HO);
        #pragma unroll
        for (int hh = 0; hh < HEADS; hh++) {
            float we = wsm[hh][e];
            float2 v0 = __half22float2(fr[hh * 384 + tid]);
            a0.x = fmaf(we, v0.x, a0.x);
            a0.y = fmaf(we, v0.y, a0.y);
            if (tid < 128) {
                float2 v1 = __half22float2(fr[hh * 384 + 256 + tid]);
                a1.x = fmaf(we, v1.x, a1.x);
                a1.y = fmaf(we, v1.y, a1.y);
            }
        }
    }
    {
        size_t base = (size_t)(g * NPG + NATOM) * NH;
        *(float2*)&g_h[base + 2 * tid] = make_float2(a0.x * 0.125f, a0.y * 0.125f);
        if (tid < 128)
            *(float2*)&g_h[base + 512 + 2 * tid] = make_float2(a1.x * 0.125f, a1.y * 0.125f);
    }
}

// ---------------- GRU projections: tiled fp32 GEMM (32-col tiles, 144 blocks) ----------------
__global__ __launch_bounds__(256) void gru_gemm_k(
    const float* __restrict__ W_ih, const float* __restrict__ W_hh,
    const float* __restrict__ b_ih, const float* __restrict__ b_hh,
    const int* __restrict__ vnid)
{
    __shared__ float As[32][132];
    __shared__ float Bs[32][36];
    const int jb  = blockIdx.x * 32;        // 144 blocks
    const int sel = (jb >= H3) ? 1 : 0;
    const int j0  = sel ? jb - H3 : jb;
    const float* __restrict__ W    = sel ? W_hh : W_ih;
    const float* __restrict__ bias = sel ? b_hh : b_ih;
    float* __restrict__ Cout       = sel ? g_gh : g_gi;

    const int tid = threadIdx.x;
    const int ty = tid >> 4, tx = tid & 15;
    float acc[8][2];
    #pragma unroll
    for (int i = 0; i < 8; i++) { acc[i][0] = 0.f; acc[i][1] = 0.f; }

    for (int k0 = 0; k0 < NH; k0 += 32) {
        #pragma unroll
        for (int l = 0; l < 4; l++) {
            int f = tid * 4 + l;
            int r = f >> 3;
            int kv = (f & 7) * 4;
            const float* arow = sel ? (g_mol + (size_t)r * NH)
                                    : (g_h + (size_t)vnid[r] * NH);
            float4 v = *(const float4*)(arow + k0 + kv);
            As[kv + 0][r] = v.x; As[kv + 1][r] = v.y;
            As[kv + 2][r] = v.z; As[kv + 3][r] = v.w;
        }
        {
            int f = tid;            // 256 float4 = 32 cols x 32 k
            int c = f >> 3;
            int kv = (f & 7) * 4;
            float4 v = *(const float4*)(W + (size_t)(j0 + c) * NH + k0 + kv);
            Bs[kv + 0][c] = v.x; Bs[kv + 1][c] = v.y;
            Bs[kv + 2][c] = v.z; Bs[kv + 3][c] = v.w;
        }
        __syncthreads();
        #pragma unroll
        for (int k = 0; k < 32; k++) {
            float a[8], b[2];
            *(float4*)&a[0] = *(float4*)&As[k][ty * 8];
            *(float4*)&a[4] = *(float4*)&As[k][ty * 8 + 4];
            b[0] = Bs[k][tx * 2];
            b[1] = Bs[k][tx * 2 + 1];
            #pragma unroll
            for (int i = 0; i < 8; i++) {
                acc[i][0] = fmaf(a[i], b[0], acc[i][0]);
                acc[i][1] = fmaf(a[i], b[1], acc[i][1]);
            }
        }
        __syncthreads();
    }
    #pragma unroll
    for (int i = 0; i < 8; i++) {
        int b = ty * 8 + i;
        #pragma unroll
        for (int j = 0; j < 2; j++) {
            int jj = j0 + tx * 2 + j;
            Cout[(size_t)b * H3 + jj] = acc[i][j] + bias[jj];
        }
    }
}

// ---------------- GRU combine + relu ----------------
__global__ void gru_combine_k(float* __restrict__ out_mol, int write_out)
{
    int i = blockIdx.x * 256 + threadIdx.x;
    int b = i / NH, k = i % NH;
    size_t base = (size_t)b * H3;
    float ir = g_gi[base + k], iz = g_gi[base + NH + k], in_ = g_gi[base + 2 * NH + k];
    float hr = g_gh[base + k], hz = g_gh[base + NH + k], hn  = g_gh[base + 2 * NH + k];
    float r  = 1.f / (1.f + expf(-(ir + hr)));
    float z  = 1.f / (1.f + expf(-(iz + hz)));
    float nn = tanhf(in_ + r * hn);
    float hprev = g_mol[i];
    float hnew  = (1.f - z) * nn + z * hprev;
    hnew = fmaxf(hnew, 0.f);
    g_mol[i] = hnew;
    if (write_out) out_mol[i] = hnew;
}

// ---------------- launch ----------------
extern "C" void kernel_launch(void* const* d_in, const int* in_sizes, int n_in,
                              void* d_out, int out_size)
{
    const float* h_nodes  = (const float*)d_in[0];
    const float* mol_feat = (const float*)d_in[1];
    const float* W_src    = (const float*)d_in[2];
    const float* b_src    = (const float*)d_in[3];
    const float* W_dst    = (const float*)d_in[4];
    const float* b_dst    = (const float*)d_in[5];
    const float* attn_a   = (const float*)d_in[6];
    const float* W_ih     = (const float*)d_in[7];
    const float* W_hh     = (const float*)d_in[8];
    const float* b_ih     = (const float*)d_in[9];
    const float* b_hh     = (const float*)d_in[10];
    const int*   src      = (const int*)d_in[11];
    const int*   dst      = (const int*)d_in[12];
    const int*   vnid     = (const int*)d_in[13];
    float* out = (float*)d_out;

    cudaFuncSetAttribute(gemm_mma, cudaFuncAttributeMaxDynamicSharedMemorySize, GEMM_SMEM);

    {
        long tot = (long)NN * NH + (long)BB * NH;
        init_k<<<(int)((tot + 255) / 256), 256>>>(h_nodes, mol_feat);
    }
    {
        dim3 gr(HO / 32, NH / 32, 6);
        transpose_conv_k<<<gr, dim3(32, 8)>>>(W_src, W_dst);
    }
    conv_attn_k<<<(TSTEP * HEADS * NH + 255) / 256, 256>>>(attn_a);

    __half *pBf, *pAh, *pAf, *pAfv, *pFsh, *pFdh, *pFdv;
    cudaGetSymbolAddress((void**)&pBf, g_Bf);
    cudaGetSymbolAddress((void**)&pAh, g_ah);
    cudaGetSymbolAddress((void**)&pAf, g_Af);
    cudaGetSymbolAddress((void**)&pAfv, g_Afv);
    cudaGetSymbolAddress((void**)&pFsh, g_fsh);
    cudaGetSymbolAddress((void**)&pFdh, g_fdh);
    cudaGetSymbolAddress((void**)&pFdv, g_fdv);

    const size_t msz = (size_t)HO * NH;
    for (int t = 0; t < TSTEP; t++) {
        if (t < TSTEP - 1) {
            dim3 gg(HO / 128, NN / 128, 2);   // (48, 49, 2)
            gemm_mma<<<gg, 256, GEMM_SMEM>>>(pAf, pBf + (size_t)(t * 2) * msz,
                                             b_src + (size_t)t * HO,
                                             b_dst + (size_t)t * HO, pFsh, pFdh);
            node_aggregate_fused_k<<<NN, 256>>>(src, dst,
                                                pAh + (size_t)t * HEADS * NH, out, t);
        } else {
            dim3 gg(HO / 128, NN / 128, 1);
            gemm_mma<<<gg, 256, GEMM_SMEM>>>(pAf, pBf + (size_t)(t * 2) * msz,
                                             b_src + (size_t)t * HO,
                                             b_src + (size_t)t * HO, pFsh, pFsh);
            dim3 gv(HO / 128, 1, 1);
            gemm_mma<<<gv, 256, GEMM_SMEM>>>(pAfv, pBf + (size_t)(t * 2 + 1) * msz,
                                             b_dst + (size_t)t * HO,
                                             b_dst + (size_t)t * HO, pFdv, pFdv);
            node_aggregate_virt_fused_k<<<BB, 256>>>(src,
                                                     pAh + (size_t)t * HEADS * NH, out, t);
        }
        gru_gemm_k<<<(H3 * 2) / 32, 256>>>(W_ih + (size_t)t * H3 * NH,
                                           W_hh + (size_t)t * H3 * NH,
                                           b_ih + (size_t)t * H3,
                                           b_hh + (size_t)t * H3, vnid);
        gru_combine_k<<<BB * NH / 256, 256>>>(out, t == TSTEP - 1);
    }
}

// round 16
// speedup vs baseline: 1.5235x; 1.0257x over previous
#include <cuda_runtime.h>
#include <cuda_bf16.h>
#include <cuda_fp16.h>
#include <math.h>
#include <stdint.h>

// ---------------- problem constants ----------------
#define NH    768            // H
#define HEADS 8
#define HO    6144           // HEADS*H
#define TSTEP 3
#define BB    128            // molecules
#define NATOM 48
#define NPG   49             // nodes per graph
#define EPG   144            // edges per graph
#define EINTRA 96
#define NN    6272           // B*NPG nodes
#define EE    18432          // B*EPG edges
#define H3    2304           // 3*H

// ---------------- device scratch (no allocation allowed) ----------------
__device__ float  g_h   [(size_t)NN * NH];    // node features fp32 (only virtual rows maintained)
__device__ __half g_fsh [(size_t)NN * HO];    // feat_src  [N, heads*H] fp16
__device__ __half g_fdh [(size_t)NN * HO];    // feat_dst  [N, heads*H] fp16
__device__ __half g_fdv [(size_t)BB * HO];    // feat_dst for virtual nodes only (t=2)
__device__ float  g_mol [(size_t)BB * NH];
__device__ float  g_gi  [(size_t)BB * H3];
__device__ float  g_gh  [(size_t)BB * H3];

// fp16 operands for tensor-core GEMM
__device__ __half g_Af [(size_t)NN * NH];     // A in fp16
__device__ __half g_Afv[(size_t)BB * NH];     // compact virtual rows of A (fp16)
__device__ __half g_Bf [(size_t)6 * HO * NH]; // 6 weight mats, [N=6144,K=768] fp16
__device__ __half g_ah [(size_t)TSTEP * HEADS * NH];   // attn_a in fp16

// ---------------- init ----------------
__global__ void init_k(const float* __restrict__ h_nodes, const float* __restrict__ mol)
{
    long i = (long)blockIdx.x * 256 + threadIdx.x;
    const long tot = (long)NN * NH;
    if (i < tot) {
        g_Af[i] = __float2half_rn(h_nodes[i]);
    } else if (i < tot + (long)BB * NH) {
        g_mol[i - tot] = mol[i - tot];
    }
}

// ---------------- attn_a -> fp16 ----------------
__global__ void conv_attn_k(const float* __restrict__ attn_a)
{
    int i = blockIdx.x * 256 + threadIdx.x;
    if (i < TSTEP * HEADS * NH) g_ah[i] = __float2half_rn(attn_a[i]);
}

// ---------------- transpose + fp16-convert weight matrices ----------------
__global__ void transpose_conv_k(const float* __restrict__ Wsrc, const float* __restrict__ Wdst)
{
    const int mat = blockIdx.z;                    // t*2 + sel
    const float* W = ((mat & 1) ? Wdst : Wsrc) + (size_t)(mat >> 1) * NH * HO;
    __shared__ float tile[32][33];
    const int n0 = blockIdx.x * 32, k0 = blockIdx.y * 32;
    const int tx = threadIdx.x, ty = threadIdx.y;  // 32 x 8
    #pragma unroll
    for (int i = ty; i < 32; i += 8)
        tile[i][tx] = W[(size_t)(k0 + i) * HO + n0 + tx];
    __syncthreads();
    const size_t base = (size_t)mat * HO * NH;
    #pragma unroll
    for (int i = ty; i < 32; i += 8)
        g_Bf[base + (size_t)(n0 + i) * NH + k0 + tx] = __float2half_rn(tile[tx][i]);
}

// ================= mma.sync fp16 GEMM (proven config) ==========
#define KC      32
#define ST_AF   0
#define ST_BF   8192
#define ST_SZ   16384
#define NSTAGE  6
#define GEMM_SMEM (NSTAGE * ST_SZ)         // 96 KB

__device__ __forceinline__ void cp16(uint32_t saddr, const void* gaddr) {
    asm volatile("cp.async.cg.shared.global [%0], [%1], 16;" :: "r"(saddr), "l"(gaddr) : "memory");
}
__device__ __forceinline__ void cp_commit() { asm volatile("cp.async.commit_group;" ::: "memory"); }
template <int N> __device__ __forceinline__ void cp_wait() {
    asm volatile("cp.async.wait_group %0;" :: "n"(N) : "memory");
}
__device__ __forceinline__ void ldsm4(uint32_t r[4], uint32_t addr) {
    asm volatile("ldmatrix.sync.aligned.m8n8.x4.shared.b16 {%0,%1,%2,%3}, [%4];"
        : "=r"(r[0]), "=r"(r[1]), "=r"(r[2]), "=r"(r[3]) : "r"(addr));
}
__device__ __forceinline__ void mma_f16(float c[4], const uint32_t a[4], const uint32_t b[2]) {
    asm volatile("mma.sync.aligned.m16n8k16.row.col.f32.f16.f16.f32 "
        "{%0,%1,%2,%3}, {%4,%5,%6,%7}, {%8,%9}, {%0,%1,%2,%3};"
        : "+f"(c[0]), "+f"(c[1]), "+f"(c[2]), "+f"(c[3])
        : "r"(a[0]), "r"(a[1]), "r"(a[2]), "r"(a[3]), "r"(b[0]), "r"(b[1]));
}
__device__ __forceinline__ uint32_t smem_u32(const void* p) {
    uint32_t a;
    asm("{ .reg .u64 t; cvta.to.shared.u64 t, %1; cvt.u32.u64 %0, t; }" : "=r"(a) : "l"(p));
    return a;
}

// nvy: if blockIdx.y == nvy, this block computes the compact virtual-fd tile:
//      A -> Av (128 rows), B -> second weight matrix, C -> Cv, bias -> bias1.
__global__ __launch_bounds__(256, 2) void gemm_mma(
    const __half* __restrict__ A_in,
    const __half* __restrict__ Bf_base,
    const float* __restrict__ bias0, const float* __restrict__ bias1,
    __half* __restrict__ C0, __half* __restrict__ C1,
    const __half* __restrict__ Av, __half* __restrict__ Cv, int nvy)
{
    extern __shared__ char sm[];
    const uint32_t sb = smem_u32(sm);
    const int tid  = threadIdx.x;
    const int wid  = tid >> 5, lane = tid & 31;
    int m0 = blockIdx.y * 128;
    const int n0 = blockIdx.x * 128;
    const int sel  = blockIdx.z;
    const size_t msz = (size_t)HO * NH;
    const __half* __restrict__ A  = A_in;
    const __half* __restrict__ Bf = Bf_base + (size_t)sel * msz;
    const float* __restrict__ bias = sel ? bias1 : bias0;
    __half* __restrict__ C = sel ? C1 : C0;
    if ((int)blockIdx.y == nvy) {
        A = Av; m0 = 0;
        Bf = Bf_base + msz;
        bias = bias1;
        C = Cv;
    }
    const int wm   = wid & 3;
    const int wn   = wid >> 2;

    const int seg0 = tid * 2;
    const int r0l  = seg0 >> 2,  c0l = seg0 & 3;
    const int r1l  = (seg0 + 1) >> 2, c1l = (seg0 + 1) & 3;
    const uint32_t so0 = r0l * 64 + ((c0l ^ (r0l & 3)) << 4);
    const uint32_t so1 = r1l * 64 + ((c1l ^ (r1l & 3)) << 4);

    #define LOAD_STAGE(stg, k0) do {                                              \
        uint32_t _b = sb + (stg) * ST_SZ;                                         \
        size_t ga0 = (size_t)(m0 + r0l) * NH + (k0) + c0l * 8;                    \
        size_t ga1 = (size_t)(m0 + r1l) * NH + (k0) + c1l * 8;                    \
        size_t gb0 = (size_t)(n0 + r0l) * NH + (k0) + c0l * 8;                    \
        size_t gb1 = (size_t)(n0 + r1l) * NH + (k0) + c1l * 8;                    \
        cp16(_b + ST_AF + so0, A + ga0);                                          \
        cp16(_b + ST_AF + so1, A + ga1);                                          \
        cp16(_b + ST_BF + so0, Bf + gb0);                                         \
        cp16(_b + ST_BF + so1, Bf + gb1);                                         \
    } while (0)

    const int sub = lane >> 3, rin = lane & 7;
    const int aRow0 = wm * 32 + (sub & 1) * 8 + rin;
    const int aSegB = sub >> 1;
    const int bRow0 = wn * 64 + (sub >> 1) * 8 + rin;
    const int bSegB = sub & 1;

    float acc[16][4];
    #pragma unroll
    for (int i = 0; i < 16; i++)
        #pragma unroll
        for (int j = 0; j < 4; j++) acc[i][j] = 0.f;

    #pragma unroll
    for (int s = 0; s < NSTAGE - 1; s++) {
        LOAD_STAGE(s, s * KC);
        cp_commit();
    }

    const int NCH = NH / KC;   // 24
    int stg = 0;
    for (int kc = 0; kc < NCH; kc++) {
        cp_wait<NSTAGE - 2>();
        __syncthreads();
        if (kc + NSTAGE - 1 < NCH) {
            LOAD_STAGE((kc + NSTAGE - 1) % NSTAGE, (kc + NSTAGE - 1) * KC);
        }
        cp_commit();

        const uint32_t stb = sb + stg * ST_SZ;
        #pragma unroll
        for (int k16 = 0; k16 < 2; k16++) {
            const int ks = k16 * 2;
            uint32_t aF[2][4], bb[8][2];
            #pragma unroll
            for (int mf = 0; mf < 2; mf++) {
                int row = aRow0 + mf * 16;
                uint32_t off = row * 64 + (((ks + aSegB) ^ (row & 3)) << 4);
                ldsm4(aF[mf], stb + ST_AF + off);
            }
            #pragma unroll
            for (int pp = 0; pp < 4; pp++) {
                int row = bRow0 + pp * 16;
                uint32_t off = row * 64 + (((ks + bSegB) ^ (row & 3)) << 4);
                uint32_t t[4];
                ldsm4(t, stb + ST_BF + off);
                bb[pp * 2][0] = t[0]; bb[pp * 2][1] = t[1];
                bb[pp * 2 + 1][0] = t[2]; bb[pp * 2 + 1][1] = t[3];
            }
            #pragma unroll
            for (int mf = 0; mf < 2; mf++)
                #pragma unroll
                for (int p = 0; p < 8; p++) mma_f16(acc[mf * 8 + p], aF[mf], bb[p]);
        }
        stg = (stg + 1 == NSTAGE) ? 0 : stg + 1;
    }

    const int qrow = lane >> 2, qcol = (lane & 3) * 2;
    const int gmb = m0 + wm * 32;
    const int gnb = n0 + wn * 64;
    #pragma unroll
    for (int mf = 0; mf < 2; mf++) {
        int r0 = gmb + mf * 16 + qrow;
        #pragma unroll
        for (int p = 0; p < 8; p++) {
            int cn = gnb + p * 8 + qcol;
            float bx = bias[cn], by = bias[cn + 1];
            __half2 v0 = __floats2half2_rn(acc[mf * 8 + p][0] + bx, acc[mf * 8 + p][1] + by);
            __half2 v1 = __floats2half2_rn(acc[mf * 8 + p][2] + bx, acc[mf * 8 + p][3] + by);
            *(__half2*)&C[(size_t)r0 * HO + cn] = v0;
            *(__half2*)&C[(size_t)(r0 + 8) * HO + cn] = v1;
        }
    }
    #undef LOAD_STAGE
}

// ---- batched (x4) logit computation: 4 edges per warp pass, high MLP ----
// Computes logits for edges [e0, min(e0+4, deg)) of head `wid` and writes wsm.
__device__ __forceinline__ void logit_batch4(
    const int* __restrict__ esrc, int e0, int deg,
    const uint4* __restrict__ fd4, const uint4* __restrict__ aa4,
    int wid, int lane, float* __restrict__ wrow)
{
    const __half2 hz  = __float2half2_rn(0.f);
    const __half2 hsl = __float2half2_rn(0.2f);
    const uint4* fsp[4];
    #pragma unroll
    for (int q = 0; q < 4; q++) {
        int ee = (e0 + q < deg) ? (e0 + q) : (deg - 1);
        fsp[q] = ((const uint4*)(g_fsh + (size_t)esrc[ee] * HO)) + wid * 96;
    }
    float ac[4] = {0.f, 0.f, 0.f, 0.f};
    #pragma unroll
    for (int it = 0; it < 3; it++) {
        int idx = it * 32 + lane;
        uint4 D = fd4[idx], V = aa4[idx];
        const __half2* hD = (const __half2*)&D;
        const __half2* hV = (const __half2*)&V;
        #pragma unroll
        for (int q = 0; q < 4; q++) {
            uint4 Av2 = fsp[q][idx];
            const __half2* hA = (const __half2*)&Av2;
            #pragma unroll
            for (int j = 0; j < 4; j++) {
                __half2 x  = __hadd2(hA[j], hD[j]);
                __half2 lk = __hfma2(__hmin2(x, hz), hsl, __hmax2(x, hz));
                float2 f = __half22float2(__hmul2(lk, hV[j]));
                ac[q] += f.x + f.y;
            }
        }
    }
    #pragma unroll
    for (int q = 0; q < 4; q++) {
        #pragma unroll
        for (int o = 16; o > 0; o >>= 1) ac[q] += __shfl_xor_sync(0xFFFFFFFFu, ac[q], o);
        if (lane == 0 && e0 + q < deg) wrow[e0 + q] = ac[q];
    }
}

// ---------------- FUSED: logits + softmax + aggregation (t<2) ----------------
__global__ __launch_bounds__(256) void node_aggregate_fused_k(
    const int* __restrict__ src, const int* __restrict__ dst,
    const __half* __restrict__ aa_t, float* __restrict__ out, int t)
{
    const int n = blockIdx.x;
    const int tid = threadIdx.x;
    const int wid = tid >> 5, lane = tid & 31;
    __shared__ int    cnt;
    __shared__ int    eidx[EPG];
    __shared__ int    esrc[EPG];
    __shared__ float  wsm[HEADS][EPG];
    __shared__ __align__(16) __half fd_s[HO];
    __shared__ __align__(16) __half aa_s[HO];

    const int g = n / NPG;
    const bool isv = (n - g * NPG) == NATOM;
    if (tid == 0) cnt = 0;
    {
        const uint4* fdg = (const uint4*)(g_fdh + (size_t)n * HO);
        const uint4* aag = (const uint4*)aa_t;
        uint4* fds = (uint4*)fd_s;
        uint4* aas = (uint4*)aa_s;
        #pragma unroll
        for (int i = 0; i < 3; i++) {
            fds[tid + 256 * i] = fdg[tid + 256 * i];
            aas[tid + 256 * i] = aag[tid + 256 * i];
        }
    }
    __syncthreads();
    if (tid < EPG) {
        int e = g * EPG + tid;
        if (dst[e] == n) {
            int p = atomicAdd(&cnt, 1);
            eidx[p] = e;
            esrc[p] = src[e];
        }
    }
    __syncthreads();
    const int deg = cnt;

    // logits: warp wid = head wid, 4 edges per pass
    const uint4* fd4 = ((const uint4*)fd_s) + wid * 96;
    const uint4* aa4 = ((const uint4*)aa_s) + wid * 96;
    for (int e0 = 0; e0 < deg; e0 += 4)
        logit_batch4(esrc, e0, deg, fd4, aa4, wid, lane, wsm[wid]);
    __syncwarp();

    // warp-local softmax
    if (deg > 0) {
        float lm = -1e30f;
        for (int i = lane; i < deg; i += 32) lm = fmaxf(lm, wsm[wid][i]);
        #pragma unroll
        for (int o = 16; o > 0; o >>= 1) lm = fmaxf(lm, __shfl_xor_sync(0xFFFFFFFFu, lm, o));
        float ls = 0.f;
        for (int i = lane; i < deg; i += 32) {
            float ex = expf(wsm[wid][i] - lm);
            wsm[wid][i] = ex;
            ls += ex;
        }
        #pragma unroll
        for (int o = 16; o > 0; o >>= 1) ls += __shfl_xor_sync(0xFFFFFFFFu, ls, o);
        float inv = 1.f / ls;
        for (int i = lane; i < deg; i += 32) wsm[wid][i] *= inv;
    }
    __syncthreads();

    // attention mean -> direct output (virtual nodes only)
    if (isv && tid < deg) {
        float s = 0.f;
        #pragma unroll
        for (int hh = 0; hh < HEADS; hh++) s += wsm[hh][tid];
        int j = eidx[tid] - g * EPG - EINTRA;   // 0..47
        out[(size_t)BB * NH + (size_t)t * BB * NATOM + g * NATOM + j] = s * 0.125f;
    }

    // feature aggregation
    float2 a0 = make_float2(0.f, 0.f), a1 = make_float2(0.f, 0.f);
    for (int e = 0; e < deg; e++) {
        const __half2* fr = (const __half2*)(g_fsh + (size_t)esrc[e] * HO);
        #pragma unroll
        for (int hh = 0; hh < HEADS; hh++) {
            float we = wsm[hh][e];
            float2 v0 = __half22float2(fr[hh * 384 + tid]);
            a0.x = fmaf(we, v0.x, a0.x);
            a0.y = fmaf(we, v0.y, a0.y);
            if (tid < 128) {
                float2 v1 = __half22float2(fr[hh * 384 + 256 + tid]);
                a1.x = fmaf(we, v1.x, a1.x);
                a1.y = fmaf(we, v1.y, a1.y);
            }
        }
    }
    {
        size_t base = (size_t)n * NH;
        float2 o0 = make_float2(a0.x * 0.125f, a0.y * 0.125f);
        __half2 h0 = __floats2half2_rn(o0.x, o0.y);
        ((__half2*)(g_Af + base))[tid] = h0;
        if (isv) {
            *(float2*)&g_h[base + 2 * tid] = o0;
            ((__half2*)(g_Afv + (size_t)g * NH))[tid] = h0;
        }
        if (tid < 128) {
            float2 o1 = make_float2(a1.x * 0.125f, a1.y * 0.125f);
            __half2 h1 = __floats2half2_rn(o1.x, o1.y);
            ((__half2*)(g_Af + base))[256 + tid] = h1;
            if (isv) {
                *(float2*)&g_h[base + 512 + 2 * tid] = o1;
                ((__half2*)(g_Afv + (size_t)g * NH))[256 + tid] = h1;
            }
        }
    }
}

// ---------------- FUSED virtual-only path (t=2) ----------------
__global__ __launch_bounds__(256) void node_aggregate_virt_fused_k(
    const int* __restrict__ src, const __half* __restrict__ aa_t,
    float* __restrict__ out, int t)
{
    const int g = blockIdx.x;
    const int tid = threadIdx.x;
    const int wid = tid >> 5, lane = tid & 31;
    __shared__ int    esrc[NATOM];
    __shared__ float  wsm[HEADS][NATOM];
    __shared__ __align__(16) __half fd_s[HO];
    __shared__ __align__(16) __half aa_s[HO];

    {
        const uint4* fdg = (const uint4*)(g_fdv + (size_t)g * HO);
        const uint4* aag = (const uint4*)aa_t;
        uint4* fds = (uint4*)fd_s;
        uint4* aas = (uint4*)aa_s;
        #pragma unroll
        for (int i = 0; i < 3; i++) {
            fds[tid + 256 * i] = fdg[tid + 256 * i];
            aas[tid + 256 * i] = aag[tid + 256 * i];
        }
    }
    if (tid < NATOM) esrc[tid] = src[g * EPG + EINTRA + tid];
    __syncthreads();

    const uint4* fd4 = ((const uint4*)fd_s) + wid * 96;
    const uint4* aa4 = ((const uint4*)aa_s) + wid * 96;
    for (int e0 = 0; e0 < NATOM; e0 += 4)
        logit_batch4(esrc, e0, NATOM, fd4, aa4, wid, lane, wsm[wid]);
    __syncwarp();

    {
        float lm = -1e30f;
        for (int i = lane; i < NATOM; i += 32) lm = fmaxf(lm, wsm[wid][i]);
        #pragma unroll
        for (int o = 16; o > 0; o >>= 1) lm = fmaxf(lm, __shfl_xor_sync(0xFFFFFFFFu, lm, o));
        float ls = 0.f;
        for (int i = lane; i < NATOM; i += 32) {
            float ex = expf(wsm[wid][i] - lm);
            wsm[wid][i] = ex;
            ls += ex;
        }
        #pragma unroll
        for (int o = 16; o > 0; o >>= 1) ls += __shfl_xor_sync(0xFFFFFFFFu, ls, o);
        float inv = 1.f / ls;
        for (int i = lane; i < NATOM; i += 32) wsm[wid][i] *= inv;
    }
    __syncthreads();

    if (tid < NATOM) {
        float s = 0.f;
        #pragma unroll
        for (int hh = 0; hh < HEADS; hh++) s += wsm[hh][tid];
        out[(size_t)BB * NH + (size_t)t * BB * NATOM + g * NATOM + tid] = s * 0.125f;
    }

    float2 a0 = make_float2(0.f, 0.f), a1 = make_float2(0.f, 0.f);
    for (int e = 0; e < NATOM; e++) {
        const __half2* fr = (const __half2*)(g_fsh + (size_t)esrc[e] * HO);
        #pragma unroll
        for (int hh = 0; hh < HEADS; hh++) {
            float we = wsm[hh][e];
            float2 v0 = __half22float2(fr[hh * 384 + tid]);
            a0.x = fmaf(we, v0.x, a0.x);
            a0.y = fmaf(we, v0.y, a0.y);
            if (tid < 128) {
                float2 v1 = __half22float2(fr[hh * 384 + 256 + tid]);
                a1.x = fmaf(we, v1.x, a1.x);
                a1.y = fmaf(we, v1.y, a1.y);
            }
        }
    }
    {
        size_t base = (size_t)(g * NPG + NATOM) * NH;
        *(float2*)&g_h[base + 2 * tid] = make_float2(a0.x * 0.125f, a0.y * 0.125f);
        if (tid < 128)
            *(float2*)&g_h[base + 512 + 2 * tid] = make_float2(a1.x * 0.125f, a1.y * 0.125f);
    }
}

// ---------------- GRU projections: tiled fp32 GEMM (32-col tiles, 144 blocks) ----------------
__global__ __launch_bounds__(256) void gru_gemm_k(
    const float* __restrict__ W_ih, const float* __restrict__ W_hh,
    const float* __restrict__ b_ih, const float* __restrict__ b_hh,
    const int* __restrict__ vnid)
{
    __shared__ float As[32][132];
    __shared__ float Bs[32][36];
    const int jb  = blockIdx.x * 32;        // 144 blocks
    const int sel = (jb >= H3) ? 1 : 0;
    const int j0  = sel ? jb - H3 : jb;
    const float* __restrict__ W    = sel ? W_hh : W_ih;
    const float* __restrict__ bias = sel ? b_hh : b_ih;
    float* __restrict__ Cout       = sel ? g_gh : g_gi;

    const int tid = threadIdx.x;
    const int ty = tid >> 4, tx = tid & 15;
    float acc[8][2];
    #pragma unroll
    for (int i = 0; i < 8; i++) { acc[i][0] = 0.f; acc[i][1] = 0.f; }

    for (int k0 = 0; k0 < NH; k0 += 32) {
        #pragma unroll
        for (int l = 0; l < 4; l++) {
            int f = tid * 4 + l;
            int r = f >> 3;
            int kv = (f & 7) * 4;
            const float* arow = sel ? (g_mol + (size_t)r * NH)
                                    : (g_h + (size_t)vnid[r] * NH);
            float4 v = *(const float4*)(arow + k0 + kv);
            As[kv + 0][r] = v.x; As[kv + 1][r] = v.y;
            As[kv + 2][r] = v.z; As[kv + 3][r] = v.w;
        }
        {
            int f = tid;
            int c = f >> 3;
            int kv = (f & 7) * 4;
            float4 v = *(const float4*)(W + (size_t)(j0 + c) * NH + k0 + kv);
            Bs[kv + 0][c] = v.x; Bs[kv + 1][c] = v.y;
            Bs[kv + 2][c] = v.z; Bs[kv + 3][c] = v.w;
        }
        __syncthreads();
        #pragma unroll
        for (int k = 0; k < 32; k++) {
            float a[8], b[2];
            *(float4*)&a[0] = *(float4*)&As[k][ty * 8];
            *(float4*)&a[4] = *(float4*)&As[k][ty * 8 + 4];
            b[0] = Bs[k][tx * 2];
            b[1] = Bs[k][tx * 2 + 1];
            #pragma unroll
            for (int i = 0; i < 8; i++) {
                acc[i][0] = fmaf(a[i], b[0], acc[i][0]);
                acc[i][1] = fmaf(a[i], b[1], acc[i][1]);
            }
        }
        __syncthreads();
    }
    #pragma unroll
    for (int i = 0; i < 8; i++) {
        int b = ty * 8 + i;
        #pragma unroll
        for (int j = 0; j < 2; j++) {
            int jj = j0 + tx * 2 + j;
            Cout[(size_t)b * H3 + jj] = acc[i][j] + bias[jj];
        }
    }
}

// ---------------- GRU combine + relu ----------------
__global__ void gru_combine_k(float* __restrict__ out_mol, int write_out)
{
    int i = blockIdx.x * 256 + threadIdx.x;
    int b = i / NH, k = i % NH;
    size_t base = (size_t)b * H3;
    float ir = g_gi[base + k], iz = g_gi[base + NH + k], in_ = g_gi[base + 2 * NH + k];
    float hr = g_gh[base + k], hz = g_gh[base + NH + k], hn  = g_gh[base + 2 * NH + k];
    float r  = 1.f / (1.f + expf(-(ir + hr)));
    float z  = 1.f / (1.f + expf(-(iz + hz)));
    float nn = tanhf(in_ + r * hn);
    float hprev = g_mol[i];
    float hnew  = (1.f - z) * nn + z * hprev;
    hnew = fmaxf(hnew, 0.f);
    g_mol[i] = hnew;
    if (write_out) out_mol[i] = hnew;
}

// ---------------- launch ----------------
extern "C" void kernel_launch(void* const* d_in, const int* in_sizes, int n_in,
                              void* d_out, int out_size)
{
    const float* h_nodes  = (const float*)d_in[0];
    const float* mol_feat = (const float*)d_in[1];
    const float* W_src    = (const float*)d_in[2];
    const float* b_src    = (const float*)d_in[3];
    const float* W_dst    = (const float*)d_in[4];
    const float* b_dst    = (const float*)d_in[5];
    const float* attn_a   = (const float*)d_in[6];
    const float* W_ih     = (const float*)d_in[7];
    const float* W_hh     = (const float*)d_in[8];
    const float* b_ih     = (const float*)d_in[9];
    const float* b_hh     = (const float*)d_in[10];
    const int*   src      = (const int*)d_in[11];
    const int*   dst      = (const int*)d_in[12];
    const int*   vnid     = (const int*)d_in[13];
    float* out = (float*)d_out;

    cudaFuncSetAttribute(gemm_mma, cudaFuncAttributeMaxDynamicSharedMemorySize, GEMM_SMEM);

    {
        long tot = (long)NN * NH + (long)BB * NH;
        init_k<<<(int)((tot + 255) / 256), 256>>>(h_nodes, mol_feat);
    }
    {
        dim3 gr(HO / 32, NH / 32, 6);
        transpose_conv_k<<<gr, dim3(32, 8)>>>(W_src, W_dst);
    }
    conv_attn_k<<<(TSTEP * HEADS * NH + 255) / 256, 256>>>(attn_a);

    __half *pBf, *pAh, *pAf, *pAfv, *pFsh, *pFdh, *pFdv;
    cudaGetSymbolAddress((void**)&pBf, g_Bf);
    cudaGetSymbolAddress((void**)&pAh, g_ah);
    cudaGetSymbolAddress((void**)&pAf, g_Af);
    cudaGetSymbolAddress((void**)&pAfv, g_Afv);
    cudaGetSymbolAddress((void**)&pFsh, g_fsh);
    cudaGetSymbolAddress((void**)&pFdh, g_fdh);
    cudaGetSymbolAddress((void**)&pFdv, g_fdv);

    const size_t msz = (size_t)HO * NH;
    for (int t = 0; t < TSTEP; t++) {
        if (t < TSTEP - 1) {
            dim3 gg(HO / 128, NN / 128, 2);   // (48, 49, 2)
            gemm_mma<<<gg, 256, GEMM_SMEM>>>(pAf, pBf + (size_t)(t * 2) * msz,
                                             b_src + (size_t)t * HO,
                                             b_dst + (size_t)t * HO, pFsh, pFdh,
                                             nullptr, nullptr, -1);
            node_aggregate_fused_k<<<NN, 256>>>(src, dst,
                                                pAh + (size_t)t * HEADS * NH, out, t);
        } else {
            // fs for all nodes + fd for virtual rows, ONE launch (grid.y = 50)
            dim3 gg(HO / 128, NN / 128 + 1, 1);
            gemm_mma<<<gg, 256, GEMM_SMEM>>>(pAf, pBf + (size_t)(t * 2) * msz,
                                             b_src + (size_t)t * HO,
                                             b_dst + (size_t)t * HO, pFsh, pFsh,
                                             pAfv, pFdv, NN / 128);
            node_aggregate_virt_fused_k<<<BB, 256>>>(src,
                                                     pAh + (size_t)t * HEADS * NH, out, t);
        }
        gru_gemm_k<<<(H3 * 2) / 32, 256>>>(W_ih + (size_t)t * H3 * NH,
                                           W_hh + (size_t)t * H3 * NH,
                                           b_ih + (size_t)t * H3,
                                           b_hh + (size_t)t * H3, vnid);
        gru_combine_k<<<BB * NH / 256, 256>>>(out, t == TSTEP - 1);
    }
}

// round 17
// speedup vs baseline: 1.5559x; 1.0212x over previous
#include <cuda_runtime.h>
#include <cuda_bf16.h>
#include <cuda_fp16.h>
#include <math.h>
#include <stdint.h>

// ---------------- problem constants ----------------
#define NH    768            // H
#define HEADS 8
#define HO    6144           // HEADS*H
#define TSTEP 3
#define BB    128            // molecules
#define NATOM 48
#define NPG   49             // nodes per graph
#define EPG   144            // edges per graph
#define EINTRA 96
#define NN    6272           // B*NPG nodes
#define EE    18432          // B*EPG edges
#define H3    2304           // 3*H

// ---------------- device scratch (no allocation allowed) ----------------
__device__ float  g_h   [(size_t)NN * NH];    // node features fp32 (only virtual rows maintained)
__device__ __half g_fsh [(size_t)NN * HO];    // feat_src  [N, heads*H] fp16
__device__ __half g_fdh [(size_t)NN * HO];    // feat_dst  [N, heads*H] fp16
__device__ __half g_fdv [(size_t)BB * HO];    // feat_dst for virtual nodes only (t=2)
__device__ float  g_mol [(size_t)BB * NH];
__device__ float  g_gi  [(size_t)BB * H3];
__device__ float  g_gh  [(size_t)BB * H3];

// fp16 operands for tensor-core GEMM
__device__ __half g_Af [(size_t)NN * NH];     // A in fp16
__device__ __half g_Afv[(size_t)BB * NH];     // compact virtual rows of A (fp16)
__device__ __half g_Bf [(size_t)6 * HO * NH]; // 6 weight mats, [N=6144,K=768] fp16
__device__ __half g_ah [(size_t)TSTEP * HEADS * NH];   // attn_a in fp16

// ---------------- init ----------------
__global__ void init_k(const float* __restrict__ h_nodes, const float* __restrict__ mol)
{
    long i = (long)blockIdx.x * 256 + threadIdx.x;
    const long tot = (long)NN * NH;
    if (i < tot) {
        g_Af[i] = __float2half_rn(h_nodes[i]);
    } else if (i < tot + (long)BB * NH) {
        g_mol[i - tot] = mol[i - tot];
    }
}

// ---------------- attn_a -> fp16 ----------------
__global__ void conv_attn_k(const float* __restrict__ attn_a)
{
    int i = blockIdx.x * 256 + threadIdx.x;
    if (i < TSTEP * HEADS * NH) g_ah[i] = __float2half_rn(attn_a[i]);
}

// ---------------- transpose + fp16-convert weight matrices ----------------
__global__ void transpose_conv_k(const float* __restrict__ Wsrc, const float* __restrict__ Wdst)
{
    const int mat = blockIdx.z;                    // t*2 + sel
    const float* W = ((mat & 1) ? Wdst : Wsrc) + (size_t)(mat >> 1) * NH * HO;
    __shared__ float tile[32][33];
    const int n0 = blockIdx.x * 32, k0 = blockIdx.y * 32;
    const int tx = threadIdx.x, ty = threadIdx.y;  // 32 x 8
    #pragma unroll
    for (int i = ty; i < 32; i += 8)
        tile[i][tx] = W[(size_t)(k0 + i) * HO + n0 + tx];
    __syncthreads();
    const size_t base = (size_t)mat * HO * NH;
    #pragma unroll
    for (int i = ty; i < 32; i += 8)
        g_Bf[base + (size_t)(n0 + i) * NH + k0 + tx] = __float2half_rn(tile[tx][i]);
}

// ================= mma.sync fp16 GEMM (proven config) ==========
#define KC      32
#define ST_AF   0
#define ST_BF   8192
#define ST_SZ   16384
#define NSTAGE  6
#define GEMM_SMEM (NSTAGE * ST_SZ)         // 96 KB

__device__ __forceinline__ void cp16(uint32_t saddr, const void* gaddr) {
    asm volatile("cp.async.cg.shared.global [%0], [%1], 16;" :: "r"(saddr), "l"(gaddr) : "memory");
}
__device__ __forceinline__ void cp_commit() { asm volatile("cp.async.commit_group;" ::: "memory"); }
template <int N> __device__ __forceinline__ void cp_wait() {
    asm volatile("cp.async.wait_group %0;" :: "n"(N) : "memory");
}
__device__ __forceinline__ void ldsm4(uint32_t r[4], uint32_t addr) {
    asm volatile("ldmatrix.sync.aligned.m8n8.x4.shared.b16 {%0,%1,%2,%3}, [%4];"
        : "=r"(r[0]), "=r"(r[1]), "=r"(r[2]), "=r"(r[3]) : "r"(addr));
}
__device__ __forceinline__ void mma_f16(float c[4], const uint32_t a[4], const uint32_t b[2]) {
    asm volatile("mma.sync.aligned.m16n8k16.row.col.f32.f16.f16.f32 "
        "{%0,%1,%2,%3}, {%4,%5,%6,%7}, {%8,%9}, {%0,%1,%2,%3};"
        : "+f"(c[0]), "+f"(c[1]), "+f"(c[2]), "+f"(c[3])
        : "r"(a[0]), "r"(a[1]), "r"(a[2]), "r"(a[3]), "r"(b[0]), "r"(b[1]));
}
__device__ __forceinline__ uint32_t smem_u32(const void* p) {
    uint32_t a;
    asm("{ .reg .u64 t; cvta.to.shared.u64 t, %1; cvt.u32.u64 %0, t; }" : "=r"(a) : "l"(p));
    return a;
}

// nvy: if blockIdx.y == nvy, this block computes the compact virtual-fd tile.
__global__ __launch_bounds__(256, 2) void gemm_mma(
    const __half* __restrict__ A_in,
    const __half* __restrict__ Bf_base,
    const float* __restrict__ bias0, const float* __restrict__ bias1,
    __half* __restrict__ C0, __half* __restrict__ C1,
    const __half* __restrict__ Av, __half* __restrict__ Cv, int nvy)
{
    extern __shared__ char sm[];
    const uint32_t sb = smem_u32(sm);
    const int tid  = threadIdx.x;
    const int wid  = tid >> 5, lane = tid & 31;
    int m0 = blockIdx.y * 128;
    const int n0 = blockIdx.x * 128;
    const int sel  = blockIdx.z;
    const size_t msz = (size_t)HO * NH;
    const __half* __restrict__ A  = A_in;
    const __half* __restrict__ Bf = Bf_base + (size_t)sel * msz;
    const float* __restrict__ bias = sel ? bias1 : bias0;
    __half* __restrict__ C = sel ? C1 : C0;
    if ((int)blockIdx.y == nvy) {
        A = Av; m0 = 0;
        Bf = Bf_base + msz;
        bias = bias1;
        C = Cv;
    }
    const int wm   = wid & 3;
    const int wn   = wid >> 2;

    const int seg0 = tid * 2;
    const int r0l  = seg0 >> 2,  c0l = seg0 & 3;
    const int r1l  = (seg0 + 1) >> 2, c1l = (seg0 + 1) & 3;
    const uint32_t so0 = r0l * 64 + ((c0l ^ (r0l & 3)) << 4);
    const uint32_t so1 = r1l * 64 + ((c1l ^ (r1l & 3)) << 4);

    #define LOAD_STAGE(stg, k0) do {                                              \
        uint32_t _b = sb + (stg) * ST_SZ;                                         \
        size_t ga0 = (size_t)(m0 + r0l) * NH + (k0) + c0l * 8;                    \
        size_t ga1 = (size_t)(m0 + r1l) * NH + (k0) + c1l * 8;                    \
        size_t gb0 = (size_t)(n0 + r0l) * NH + (k0) + c0l * 8;                    \
        size_t gb1 = (size_t)(n0 + r1l) * NH + (k0) + c1l * 8;                    \
        cp16(_b + ST_AF + so0, A + ga0);                                          \
        cp16(_b + ST_AF + so1, A + ga1);                                          \
        cp16(_b + ST_BF + so0, Bf + gb0);                                         \
        cp16(_b + ST_BF + so1, Bf + gb1);                                         \
    } while (0)

    const int sub = lane >> 3, rin = lane & 7;
    const int aRow0 = wm * 32 + (sub & 1) * 8 + rin;
    const int aSegB = sub >> 1;
    const int bRow0 = wn * 64 + (sub >> 1) * 8 + rin;
    const int bSegB = sub & 1;

    float acc[16][4];
    #pragma unroll
    for (int i = 0; i < 16; i++)
        #pragma unroll
        for (int j = 0; j < 4; j++) acc[i][j] = 0.f;

    #pragma unroll
    for (int s = 0; s < NSTAGE - 1; s++) {
        LOAD_STAGE(s, s * KC);
        cp_commit();
    }

    const int NCH = NH / KC;   // 24
    int stg = 0;
    for (int kc = 0; kc < NCH; kc++) {
        cp_wait<NSTAGE - 2>();
        __syncthreads();
        if (kc + NSTAGE - 1 < NCH) {
            LOAD_STAGE((kc + NSTAGE - 1) % NSTAGE, (kc + NSTAGE - 1) * KC);
        }
        cp_commit();

        const uint32_t stb = sb + stg * ST_SZ;
        #pragma unroll
        for (int k16 = 0; k16 < 2; k16++) {
            const int ks = k16 * 2;
            uint32_t aF[2][4], bb[8][2];
            #pragma unroll
            for (int mf = 0; mf < 2; mf++) {
                int row = aRow0 + mf * 16;
                uint32_t off = row * 64 + (((ks + aSegB) ^ (row & 3)) << 4);
                ldsm4(aF[mf], stb + ST_AF + off);
            }
            #pragma unroll
            for (int pp = 0; pp < 4; pp++) {
                int row = bRow0 + pp * 16;
                uint32_t off = row * 64 + (((ks + bSegB) ^ (row & 3)) << 4);
                uint32_t t[4];
                ldsm4(t, stb + ST_BF + off);
                bb[pp * 2][0] = t[0]; bb[pp * 2][1] = t[1];
                bb[pp * 2 + 1][0] = t[2]; bb[pp * 2 + 1][1] = t[3];
            }
            #pragma unroll
            for (int mf = 0; mf < 2; mf++)
                #pragma unroll
                for (int p = 0; p < 8; p++) mma_f16(acc[mf * 8 + p], aF[mf], bb[p]);
        }
        stg = (stg + 1 == NSTAGE) ? 0 : stg + 1;
    }

    const int qrow = lane >> 2, qcol = (lane & 3) * 2;
    const int gmb = m0 + wm * 32;
    const int gnb = n0 + wn * 64;
    #pragma unroll
    for (int mf = 0; mf < 2; mf++) {
        int r0 = gmb + mf * 16 + qrow;
        #pragma unroll
        for (int p = 0; p < 8; p++) {
            int cn = gnb + p * 8 + qcol;
            float bx = bias[cn], by = bias[cn + 1];
            __half2 v0 = __floats2half2_rn(acc[mf * 8 + p][0] + bx, acc[mf * 8 + p][1] + by);
            __half2 v1 = __floats2half2_rn(acc[mf * 8 + p][2] + bx, acc[mf * 8 + p][3] + by);
            *(__half2*)&C[(size_t)r0 * HO + cn] = v0;
            *(__half2*)&C[(size_t)(r0 + 8) * HO + cn] = v1;
        }
    }
    #undef LOAD_STAGE
}

// ---- batched (x4) logit computation ----
__device__ __forceinline__ void logit_batch4(
    const int* __restrict__ esrc, int e0, int deg,
    const uint4* __restrict__ fd4, const uint4* __restrict__ aa4,
    int wid, int lane, float* __restrict__ wrow)
{
    const __half2 hz  = __float2half2_rn(0.f);
    const __half2 hsl = __float2half2_rn(0.2f);
    const uint4* fsp[4];
    #pragma unroll
    for (int q = 0; q < 4; q++) {
        int ee = (e0 + q < deg) ? (e0 + q) : (deg - 1);
        fsp[q] = ((const uint4*)(g_fsh + (size_t)esrc[ee] * HO)) + wid * 96;
    }
    float ac[4] = {0.f, 0.f, 0.f, 0.f};
    #pragma unroll
    for (int it = 0; it < 3; it++) {
        int idx = it * 32 + lane;
        uint4 D = fd4[idx], V = aa4[idx];
        const __half2* hD = (const __half2*)&D;
        const __half2* hV = (const __half2*)&V;
        #pragma unroll
        for (int q = 0; q < 4; q++) {
            uint4 Av2 = fsp[q][idx];
            const __half2* hA = (const __half2*)&Av2;
            #pragma unroll
            for (int j = 0; j < 4; j++) {
                __half2 x  = __hadd2(hA[j], hD[j]);
                __half2 lk = __hfma2(__hmin2(x, hz), hsl, __hmax2(x, hz));
                float2 f = __half22float2(__hmul2(lk, hV[j]));
                ac[q] += f.x + f.y;
            }
        }
    }
    #pragma unroll
    for (int q = 0; q < 4; q++) {
        #pragma unroll
        for (int o = 16; o > 0; o >>= 1) ac[q] += __shfl_xor_sync(0xFFFFFFFFu, ac[q], o);
        if (lane == 0 && e0 + q < deg) wrow[e0 + q] = ac[q];
    }
}

// ---------------- FUSED: logits + softmax + aggregation (t<2) ----------------
// ubuf (24KB) holds fd/aa during logits, then is reused for per-head partials.
__global__ __launch_bounds__(256) void node_aggregate_fused_k(
    const int* __restrict__ src, const int* __restrict__ dst,
    const __half* __restrict__ aa_t, float* __restrict__ out, int t)
{
    const int n = blockIdx.x;
    const int tid = threadIdx.x;
    const int wid = tid >> 5, lane = tid & 31;
    __shared__ int    cnt;
    __shared__ int    eidx[EPG];
    __shared__ int    esrc[EPG];
    __shared__ float  wsm[HEADS][EPG];
    __shared__ __align__(16) char ubuf[24576];   // fd_s(12K)+aa_s(12K) | part(24K)

    __half* fd_s = (__half*)ubuf;
    __half* aa_s = (__half*)(ubuf + 12288);

    const int g = n / NPG;
    const bool isv = (n - g * NPG) == NATOM;
    if (tid == 0) cnt = 0;
    {
        const uint4* fdg = (const uint4*)(g_fdh + (size_t)n * HO);
        const uint4* aag = (const uint4*)aa_t;
        uint4* fds = (uint4*)fd_s;
        uint4* aas = (uint4*)aa_s;
        #pragma unroll
        for (int i = 0; i < 3; i++) {
            fds[tid + 256 * i] = fdg[tid + 256 * i];
            aas[tid + 256 * i] = aag[tid + 256 * i];
        }
    }
    __syncthreads();
    if (tid < EPG) {
        int e = g * EPG + tid;
        if (dst[e] == n) {
            int p = atomicAdd(&cnt, 1);
            eidx[p] = e;
            esrc[p] = src[e];
        }
    }
    __syncthreads();
    const int deg = cnt;

    // logits
    const uint4* fd4 = ((const uint4*)fd_s) + wid * 96;
    const uint4* aa4 = ((const uint4*)aa_s) + wid * 96;
    for (int e0 = 0; e0 < deg; e0 += 4)
        logit_batch4(esrc, e0, deg, fd4, aa4, wid, lane, wsm[wid]);
    __syncwarp();

    // warp-local softmax
    if (deg > 0) {
        float lm = -1e30f;
        for (int i = lane; i < deg; i += 32) lm = fmaxf(lm, wsm[wid][i]);
        #pragma unroll
        for (int o = 16; o > 0; o >>= 1) lm = fmaxf(lm, __shfl_xor_sync(0xFFFFFFFFu, lm, o));
        float ls = 0.f;
        for (int i = lane; i < deg; i += 32) {
            float ex = expf(wsm[wid][i] - lm);
            wsm[wid][i] = ex;
            ls += ex;
        }
        #pragma unroll
        for (int o = 16; o > 0; o >>= 1) ls += __shfl_xor_sync(0xFFFFFFFFu, ls, o);
        float inv = 1.f / ls;
        for (int i = lane; i < deg; i += 32) wsm[wid][i] *= inv;
    }
    __syncthreads();   // all logit-phase reads of ubuf complete beyond here

    // attention mean -> direct output (virtual nodes only)
    if (isv && tid < deg) {
        float s = 0.f;
        #pragma unroll
        for (int hh = 0; hh < HEADS; hh++) s += wsm[hh][tid];
        int j = eidx[tid] - g * EPG - EINTRA;   // 0..47
        out[(size_t)BB * NH + (size_t)t * BB * NATOM + g * NATOM + j] = s * 0.125f;
    }

    // aggregation: thread owns uint4 u = tid + 256*j (j<3) of the 768-uint4 fs row
    int uu0 = tid, uu1 = tid + 256, uu2 = tid + 512;
    int hd0 = uu0 / 96, hd1 = uu1 / 96, hd2 = uu2 / 96;
    float acc[3][8];
    #pragma unroll
    for (int j = 0; j < 3; j++)
        #pragma unroll
        for (int q = 0; q < 8; q++) acc[j][q] = 0.f;

    for (int e = 0; e < deg; e++) {
        const uint4* fr4 = (const uint4*)(g_fsh + (size_t)esrc[e] * HO);
        float w0 = wsm[hd0][e], w1 = wsm[hd1][e], w2 = wsm[hd2][e];
        uint4 v0 = fr4[uu0], v1 = fr4[uu1], v2 = fr4[uu2];
        const __half2* h0 = (const __half2*)&v0;
        const __half2* h1 = (const __half2*)&v1;
        const __half2* h2 = (const __half2*)&v2;
        #pragma unroll
        for (int q = 0; q < 4; q++) {
            float2 f0 = __half22float2(h0[q]);
            float2 f1 = __half22float2(h1[q]);
            float2 f2 = __half22float2(h2[q]);
            acc[0][2*q]   = fmaf(w0, f0.x, acc[0][2*q]);
            acc[0][2*q+1] = fmaf(w0, f0.y, acc[0][2*q+1]);
            acc[1][2*q]   = fmaf(w1, f1.x, acc[1][2*q]);
            acc[1][2*q+1] = fmaf(w1, f1.y, acc[1][2*q+1]);
            acc[2][2*q]   = fmaf(w2, f2.x, acc[2][2*q]);
            acc[2][2*q+1] = fmaf(w2, f2.y, acc[2][2*q+1]);
        }
    }

    // spill per-head partials into ubuf (reuse), then cross-head reduce
    float4* part = (float4*)ubuf;    // [768][2] float4
    part[uu0 * 2]     = make_float4(acc[0][0], acc[0][1], acc[0][2], acc[0][3]);
    part[uu0 * 2 + 1] = make_float4(acc[0][4], acc[0][5], acc[0][6], acc[0][7]);
    part[uu1 * 2]     = make_float4(acc[1][0], acc[1][1], acc[1][2], acc[1][3]);
    part[uu1 * 2 + 1] = make_float4(acc[1][4], acc[1][5], acc[1][6], acc[1][7]);
    part[uu2 * 2]     = make_float4(acc[2][0], acc[2][1], acc[2][2], acc[2][3]);
    part[uu2 * 2 + 1] = make_float4(acc[2][4], acc[2][5], acc[2][6], acc[2][7]);
    __syncthreads();

    const float* partf = (const float*)ubuf;   // [768][8]
    size_t base = (size_t)n * NH;
    #pragma unroll
    for (int i = 0; i < 3; i++) {
        int d = tid + 256 * i;
        int c = d >> 3, l = d & 7;
        float s = 0.f;
        #pragma unroll
        for (int hh = 0; hh < HEADS; hh++) s += partf[(hh * 96 + c) * 8 + l];
        s *= 0.125f;
        g_Af[base + d] = __float2half_rn(s);
        if (isv) {
            g_h[base + d] = s;
            g_Afv[(size_t)g * NH + d] = __float2half_rn(s);
        }
    }
}

// ---------------- FUSED virtual-only path (t=2) ----------------
__global__ __launch_bounds__(256) void node_aggregate_virt_fused_k(
    const int* __restrict__ src, const __half* __restrict__ aa_t,
    float* __restrict__ out, int t)
{
    const int g = blockIdx.x;
    const int tid = threadIdx.x;
    const int wid = tid >> 5, lane = tid & 31;
    __shared__ int    esrc[NATOM];
    __shared__ float  wsm[HEADS][NATOM];
    __shared__ __align__(16) char ubuf[24576];

    __half* fd_s = (__half*)ubuf;
    __half* aa_s = (__half*)(ubuf + 12288);
    {
        const uint4* fdg = (const uint4*)(g_fdv + (size_t)g * HO);
        const uint4* aag = (const uint4*)aa_t;
        uint4* fds = (uint4*)fd_s;
        uint4* aas = (uint4*)aa_s;
        #pragma unroll
        for (int i = 0; i < 3; i++) {
            fds[tid + 256 * i] = fdg[tid + 256 * i];
            aas[tid + 256 * i] = aag[tid + 256 * i];
        }
    }
    if (tid < NATOM) esrc[tid] = src[g * EPG + EINTRA + tid];
    __syncthreads();

    const uint4* fd4 = ((const uint4*)fd_s) + wid * 96;
    const uint4* aa4 = ((const uint4*)aa_s) + wid * 96;
    for (int e0 = 0; e0 < NATOM; e0 += 4)
        logit_batch4(esrc, e0, NATOM, fd4, aa4, wid, lane, wsm[wid]);
    __syncwarp();

    {
        float lm = -1e30f;
        for (int i = lane; i < NATOM; i += 32) lm = fmaxf(lm, wsm[wid][i]);
        #pragma unroll
        for (int o = 16; o > 0; o >>= 1) lm = fmaxf(lm, __shfl_xor_sync(0xFFFFFFFFu, lm, o));
        float ls = 0.f;
        for (int i = lane; i < NATOM; i += 32) {
            float ex = expf(wsm[wid][i] - lm);
            wsm[wid][i] = ex;
            ls += ex;
        }
        #pragma unroll
        for (int o = 16; o > 0; o >>= 1) ls += __shfl_xor_sync(0xFFFFFFFFu, ls, o);
        float inv = 1.f / ls;
        for (int i = lane; i < NATOM; i += 32) wsm[wid][i] *= inv;
    }
    __syncthreads();

    if (tid < NATOM) {
        float s = 0.f;
        #pragma unroll
        for (int hh = 0; hh < HEADS; hh++) s += wsm[hh][tid];
        out[(size_t)BB * NH + (size_t)t * BB * NATOM + g * NATOM + tid] = s * 0.125f;
    }

    int uu0 = tid, uu1 = tid + 256, uu2 = tid + 512;
    int hd0 = uu0 / 96, hd1 = uu1 / 96, hd2 = uu2 / 96;
    float acc[3][8];
    #pragma unroll
    for (int j = 0; j < 3; j++)
        #pragma unroll
        for (int q = 0; q < 8; q++) acc[j][q] = 0.f;

    for (int e = 0; e < NATOM; e++) {
        const uint4* fr4 = (const uint4*)(g_fsh + (size_t)esrc[e] * HO);
        float w0 = wsm[hd0][e], w1 = wsm[hd1][e], w2 = wsm[hd2][e];
        uint4 v0 = fr4[uu0], v1 = fr4[uu1], v2 = fr4[uu2];
        const __half2* h0 = (const __half2*)&v0;
        const __half2* h1 = (const __half2*)&v1;
        const __half2* h2 = (const __half2*)&v2;
        #pragma unroll
        for (int q = 0; q < 4; q++) {
            float2 f0 = __half22float2(h0[q]);
            float2 f1 = __half22float2(h1[q]);
            float2 f2 = __half22float2(h2[q]);
            acc[0][2*q]   = fmaf(w0, f0.x, acc[0][2*q]);
            acc[0][2*q+1] = fmaf(w0, f0.y, acc[0][2*q+1]);
            acc[1][2*q]   = fmaf(w1, f1.x, acc[1][2*q]);
            acc[1][2*q+1] = fmaf(w1, f1.y, acc[1][2*q+1]);
            acc[2][2*q]   = fmaf(w2, f2.x, acc[2][2*q]);
            acc[2][2*q+1] = fmaf(w2, f2.y, acc[2][2*q+1]);
        }
    }

    float4* part = (float4*)ubuf;
    part[uu0 * 2]     = make_float4(acc[0][0], acc[0][1], acc[0][2], acc[0][3]);
    part[uu0 * 2 + 1] = make_float4(acc[0][4], acc[0][5], acc[0][6], acc[0][7]);
    part[uu1 * 2]     = make_float4(acc[1][0], acc[1][1], acc[1][2], acc[1][3]);
    part[uu1 * 2 + 1] = make_float4(acc[1][4], acc[1][5], acc[1][6], acc[1][7]);
    part[uu2 * 2]     = make_float4(acc[2][0], acc[2][1], acc[2][2], acc[2][3]);
    part[uu2 * 2 + 1] = make_float4(acc[2][4], acc[2][5], acc[2][6], acc[2][7]);
    __syncthreads();

    const float* partf = (const float*)ubuf;
    size_t base = (size_t)(g * NPG + NATOM) * NH;
    #pragma unroll
    for (int i = 0; i < 3; i++) {
        int d = tid + 256 * i;
        int c = d >> 3, l = d & 7;
        float s = 0.f;
        #pragma unroll
        for (int hh = 0; hh < HEADS; hh++) s += partf[(hh * 96 + c) * 8 + l];
        g_h[base + d] = s * 0.125f;
    }
}

// ---------------- GRU projections: tiled fp32 GEMM (32-col tiles, 144 blocks) ----------------
__global__ __launch_bounds__(256) void gru_gemm_k(
    const float* __restrict__ W_ih, const float* __restrict__ W_hh,
    const float* __restrict__ b_ih, const float* __restrict__ b_hh,
    const int* __restrict__ vnid)
{
    __shared__ float As[32][132];
    __shared__ float Bs[32][36];
    const int jb  = blockIdx.x * 32;        // 144 blocks
    const int sel = (jb >= H3) ? 1 : 0;
    const int j0  = sel ? jb - H3 : jb;
    const float* __restrict__ W    = sel ? W_hh : W_ih;
    const float* __restrict__ bias = sel ? b_hh : b_ih;
    float* __restrict__ Cout       = sel ? g_gh : g_gi;

    const int tid = threadIdx.x;
    const int ty = tid >> 4, tx = tid & 15;
    float acc[8][2];
    #pragma unroll
    for (int i = 0; i < 8; i++) { acc[i][0] = 0.f; acc[i][1] = 0.f; }

    for (int k0 = 0; k0 < NH; k0 += 32) {
        #pragma unroll
        for (int l = 0; l < 4; l++) {
            int f = tid * 4 + l;
            int r = f >> 3;
            int kv = (f & 7) * 4;
            const float* arow = sel ? (g_mol + (size_t)r * NH)
                                    : (g_h + (size_t)vnid[r] * NH);
            float4 v = *(const float4*)(arow + k0 + kv);
            As[kv + 0][r] = v.x; As[kv + 1][r] = v.y;
            As[kv + 2][r] = v.z; As[kv + 3][r] = v.w;
        }
        {
            int f = tid;
            int c = f >> 3;
            int kv = (f & 7) * 4;
            float4 v = *(const float4*)(W + (size_t)(j0 + c) * NH + k0 + kv);
            Bs[kv + 0][c] = v.x; Bs[kv + 1][c] = v.y;
            Bs[kv + 2][c] = v.z; Bs[kv + 3][c] = v.w;
        }
        __syncthreads();
        #pragma unroll
        for (int k = 0; k < 32; k++) {
            float a[8], b[2];
            *(float4*)&a[0] = *(float4*)&As[k][ty * 8];
            *(float4*)&a[4] = *(float4*)&As[k][ty * 8 + 4];
            b[0] = Bs[k][tx * 2];
            b[1] = Bs[k][tx * 2 + 1];
            #pragma unroll
            for (int i = 0; i < 8; i++) {
                acc[i][0] = fmaf(a[i], b[0], acc[i][0]);
                acc[i][1] = fmaf(a[i], b[1], acc[i][1]);
            }
        }
        __syncthreads();
    }
    #pragma unroll
    for (int i = 0; i < 8; i++) {
        int b = ty * 8 + i;
        #pragma unroll
        for (int j = 0; j < 2; j++) {
            int jj = j0 + tx * 2 + j;
            Cout[(size_t)b * H3 + jj] = acc[i][j] + bias[jj];
        }
    }
}

// ---------------- GRU combine + relu ----------------
__global__ void gru_combine_k(float* __restrict__ out_mol, int write_out)
{
    int i = blockIdx.x * 256 + threadIdx.x;
    int b = i / NH, k = i % NH;
    size_t base = (size_t)b * H3;
    float ir = g_gi[base + k], iz = g_gi[base + NH + k], in_ = g_gi[base + 2 * NH + k];
    float hr = g_gh[base + k], hz = g_gh[base + NH + k], hn  = g_gh[base + 2 * NH + k];
    float r  = 1.f / (1.f + expf(-(ir + hr)));
    float z  = 1.f / (1.f + expf(-(iz + hz)));
    float nn = tanhf(in_ + r * hn);
    float hprev = g_mol[i];
    float hnew  = (1.f - z) * nn + z * hprev;
    hnew = fmaxf(hnew, 0.f);
    g_mol[i] = hnew;
    if (write_out) out_mol[i] = hnew;
}

// ---------------- launch ----------------
extern "C" void kernel_launch(void* const* d_in, const int* in_sizes, int n_in,
                              void* d_out, int out_size)
{
    const float* h_nodes  = (const float*)d_in[0];
    const float* mol_feat = (const float*)d_in[1];
    const float* W_src    = (const float*)d_in[2];
    const float* b_src    = (const float*)d_in[3];
    const float* W_dst    = (const float*)d_in[4];
    const float* b_dst    = (const float*)d_in[5];
    const float* attn_a   = (const float*)d_in[6];
    const float* W_ih     = (const float*)d_in[7];
    const float* W_hh     = (const float*)d_in[8];
    const float* b_ih     = (const float*)d_in[9];
    const float* b_hh     = (const float*)d_in[10];
    const int*   src      = (const int*)d_in[11];
    const int*   dst      = (const int*)d_in[12];
    const int*   vnid     = (const int*)d_in[13];
    float* out = (float*)d_out;

    cudaFuncSetAttribute(gemm_mma, cudaFuncAttributeMaxDynamicSharedMemorySize, GEMM_SMEM);

    {
        long tot = (long)NN * NH + (long)BB * NH;
        init_k<<<(int)((tot + 255) / 256), 256>>>(h_nodes, mol_feat);
    }
    {
        dim3 gr(HO / 32, NH / 32, 6);
        transpose_conv_k<<<gr, dim3(32, 8)>>>(W_src, W_dst);
    }
    conv_attn_k<<<(TSTEP * HEADS * NH + 255) / 256, 256>>>(attn_a);

    __half *pBf, *pAh, *pAf, *pAfv, *pFsh, *pFdh, *pFdv;
    cudaGetSymbolAddress((void**)&pBf, g_Bf);
    cudaGetSymbolAddress((void**)&pAh, g_ah);
    cudaGetSymbolAddress((void**)&pAf, g_Af);
    cudaGetSymbolAddress((void**)&pAfv, g_Afv);
    cudaGetSymbolAddress((void**)&pFsh, g_fsh);
    cudaGetSymbolAddress((void**)&pFdh, g_fdh);
    cudaGetSymbolAddress((void**)&pFdv, g_fdv);

    const size_t msz = (size_t)HO * NH;
    for (int t = 0; t < TSTEP; t++) {
        if (t < TSTEP - 1) {
            dim3 gg(HO / 128, NN / 128, 2);   // (48, 49, 2)
            gemm_mma<<<gg, 256, GEMM_SMEM>>>(pAf, pBf + (size_t)(t * 2) * msz,
                                             b_src + (size_t)t * HO,
                                             b_dst + (size_t)t * HO, pFsh, pFdh,
                                             nullptr, nullptr, -1);
            node_aggregate_fused_k<<<NN, 256>>>(src, dst,
                                                pAh + (size_t)t * HEADS * NH, out, t);
        } else {
            dim3 gg(HO / 128, NN / 128 + 1, 1);
            gemm_mma<<<gg, 256, GEMM_SMEM>>>(pAf, pBf + (size_t)(t * 2) * msz,
                                             b_src + (size_t)t * HO,
                                             b_dst + (size_t)t * HO, pFsh, pFsh,
                                             pAfv, pFdv, NN / 128);
            node_aggregate_virt_fused_k<<<BB, 256>>>(src,
                                                     pAh + (size_t)t * HEADS * NH, out, t);
        }
        gru_gemm_k<<<(H3 * 2) / 32, 256>>>(W_ih + (size_t)t * H3 * NH,
                                           W_hh + (size_t)t * H3 * NH,
                                           b_ih + (size_t)t * H3,
                                           b_hh + (size_t)t * H3, vnid);
        gru_combine_k<<<BB * NH / 256, 256>>>(out, t == TSTEP - 1);
    }
}